// round 5
// baseline (speedup 1.0000x reference)
#include <cuda_runtime.h>
#include <cstdint>

#define Bq  256
#define Mq  512
#define Nq  8192
#define TMq 1024
#define NSPLIT 8
#define KSL (Nq/NSPLIT)      // 1024
#define S_KSPLIT 4
#define S_KSL (Nq/S_KSPLIT)  // 2048

// ---------------- device scratch (no allocations allowed) ----------------
__device__ float g_S [TMq*TMq];
__device__ float g_X [TMq*TMq];
__device__ float g_T1[TMq*TMq];
__device__ float g_T2[TMq*TMq];
__device__ float g_Spart[S_KSPLIT][2][Mq*Mq];
__device__ float g_b [Bq*2*Nq];
__device__ float g_R [Bq*TMq];
__device__ float g_Tm[Bq*TMq];
__device__ float g_x [Bq*Nq];
__device__ float g_z [Bq*TMq];   // flat [b][1024] == (b,c,m) flattened
__device__ float g_u [Bq*TMq];
__device__ float g_Ax[Bq*TMq];
__device__ float g_part[NSPLIT][Bq*TMq];
__device__ float g_v[TMq];
__device__ float g_w[TMq];
__device__ float g_lam[1];

__device__ __forceinline__ float load_rho(const float* p){
    float v = *p; v = fminf(5.f, fmaxf(-5.f, v)); return expf(v);
}
__device__ __forceinline__ float load_eps(const float* p){
    float v = *p; v = fminf(0.f, fmaxf(-5.f, v)); return expf(v);
}

// ---------------- S = block([[Sr,-Si],[Si,Sr]]) precompute ----------------
// partial: per K-slice, Sr_part = Ar Ar^T + Ai Ai^T ; Si_part = Ai Ar^T - Ar Ai^T
__global__ __launch_bounds__(256) void k_S_partial(const float* __restrict__ A){
    const float* __restrict__ Ar = A;
    const float* __restrict__ Ai = A + (size_t)Mq*Nq;
    int j0 = blockIdx.x*64, i0 = blockIdx.y*64;
    int k0 = blockIdx.z*S_KSL;
    __shared__ float sRr[16][68], sRi[16][68], sCr[16][68], sCi[16][68];
    float rr[4][4]={}, ii_[4][4]={}, ir[4][4]={}, ri[4][4]={};
    int t  = threadIdx.y*16 + threadIdx.x;
    int lr = t>>4, lc = t&15;
    for(int k=k0;k<k0+S_KSL;k+=16){
        #pragma unroll
        for(int jj=0;jj<4;jj++){
            int r = lr + (jj<<4);
            sRr[lc][r] = Ar[(size_t)(i0+r)*Nq + (k+lc)];
            sRi[lc][r] = Ai[(size_t)(i0+r)*Nq + (k+lc)];
            sCr[lc][r] = Ar[(size_t)(j0+r)*Nq + (k+lc)];
            sCi[lc][r] = Ai[(size_t)(j0+r)*Nq + (k+lc)];
        }
        __syncthreads();
        #pragma unroll
        for(int kk=0;kk<16;kk++){
            float ar_[4], ai_[4], br_[4], bi_[4];
            *(float4*)ar_ = *(const float4*)&sRr[kk][threadIdx.y*4];
            *(float4*)ai_ = *(const float4*)&sRi[kk][threadIdx.y*4];
            *(float4*)br_ = *(const float4*)&sCr[kk][threadIdx.x*4];
            *(float4*)bi_ = *(const float4*)&sCi[kk][threadIdx.x*4];
            #pragma unroll
            for(int i=0;i<4;i++)
                #pragma unroll
                for(int j=0;j<4;j++){
                    rr [i][j] += ar_[i]*br_[j];
                    ii_[i][j] += ai_[i]*bi_[j];
                    ir [i][j] += ai_[i]*br_[j];
                    ri [i][j] += ar_[i]*bi_[j];
                }
        }
        __syncthreads();
    }
    int gi = i0 + threadIdx.y*4, gj = j0 + threadIdx.x*4;
    #pragma unroll
    for(int i=0;i<4;i++)
        #pragma unroll
        for(int j=0;j<4;j++){
            g_Spart[blockIdx.z][0][(size_t)(gi+i)*Mq + gj+j] = rr[i][j] + ii_[i][j];
            g_Spart[blockIdx.z][1][(size_t)(gi+i)*Mq + gj+j] = ir[i][j] - ri[i][j];
        }
}

__global__ void k_S_combine(const float* __restrict__ log_rho){
    int idx = blockIdx.x*256 + threadIdx.x;
    if(idx >= Mq*Mq) return;
    int i = idx/Mq, j = idx%Mq;
    float sr=0.f, si=0.f;
    #pragma unroll
    for(int ks=0;ks<S_KSPLIT;ks++){ sr += g_Spart[ks][0][idx]; si += g_Spart[ks][1][idx]; }
    float rho = load_rho(log_rho);
    if(i==j) sr += 1.0f/(rho + 1e-12f);
    g_S[(size_t) i     *TMq +      j] =  sr;
    g_S[(size_t) i     *TMq + Mq + j] = -si;
    g_S[(size_t)(Mq+i) *TMq +      j] =  si;
    g_S[(size_t)(Mq+i) *TMq + Mq + j] =  sr;
}

// ---------------- power iteration for lambda_max estimate ----------------
__global__ void k_pow_init(){
    int i = blockIdx.x*256 + threadIdx.x;
    if(i < TMq) g_v[i] = 1.0f + 0.001f*(float)i;
}
__global__ void k_pow_mv(){
    int row = blockIdx.x;
    float s = 0.f;
    for(int j=threadIdx.x;j<TMq;j+=256) s += g_S[(size_t)row*TMq + j]*g_v[j];
    __shared__ float red[256];
    red[threadIdx.x] = s; __syncthreads();
    for(int o=128;o>0;o>>=1){ if(threadIdx.x<o) red[threadIdx.x]+=red[threadIdx.x+o]; __syncthreads(); }
    if(threadIdx.x==0) g_w[row] = red[0];
}
__global__ void k_pow_norm(){
    __shared__ float red[1024];
    int tid = threadIdx.x;
    float w = g_w[tid];
    red[tid] = w*w; __syncthreads();
    for(int o=512;o>0;o>>=1){ if(tid<o) red[tid]+=red[tid+o]; __syncthreads(); }
    float nn = sqrtf(red[0]);
    g_v[tid] = g_w[tid]/nn;
    if(tid==0) g_lam[0] = nn;
}
__global__ void k_X_init(){
    int idx = blockIdx.x*256 + threadIdx.x;
    if(idx >= TMq*TMq) return;
    int i = idx/TMq, j = idx%TMq;
    g_X[idx] = (i==j) ? 1.0f/(1.2f*g_lam[0]) : 0.0f;
}
__global__ void k_newton_upd(){
    int idx = blockIdx.x*256 + threadIdx.x;
    if(idx < TMq*TMq) g_X[idx] = 2.0f*g_X[idx] - g_T2[idx];
}

// ---------------- generic SGEMM: C[Md,Nd] = A[Md,Kd] @ B[Kd,Nd] ----------------
__global__ __launch_bounds__(256) void k_gemm(const float* __restrict__ Am,
                                              const float* __restrict__ Bm,
                                              float* __restrict__ Cm,
                                              int Md, int Nd, int Kd,
                                              const int* __restrict__ ns, int step){
    if(ns && step >= *ns) return;
    int n0 = blockIdx.x*64, m0 = blockIdx.y*64;
    __shared__ float sA[16][68];
    __shared__ float sB[16][64];
    float acc[4][4] = {};
    int t  = threadIdx.y*16 + threadIdx.x;
    int lr = t>>4, lc = t&15;
    int br = t>>6, bc = t&63;
    for(int k=0;k<Kd;k+=16){
        #pragma unroll
        for(int jj=0;jj<4;jj++){
            int r = lr + (jj<<4);
            sA[lc][r] = Am[(size_t)(m0+r)*Kd + k + lc];
            sB[br + jj*4][bc] = Bm[(size_t)(k + br + jj*4)*Nd + n0 + bc];
        }
        __syncthreads();
        #pragma unroll
        for(int kk=0;kk<16;kk++){
            float a_[4], b_[4];
            *(float4*)a_ = *(const float4*)&sA[kk][threadIdx.y*4];
            *(float4*)b_ = *(const float4*)&sB[kk][threadIdx.x*4];
            #pragma unroll
            for(int i=0;i<4;i++)
                #pragma unroll
                for(int j=0;j<4;j++) acc[i][j] += a_[i]*b_[j];
        }
        __syncthreads();
    }
    int mm0 = m0 + threadIdx.y*4, nn0 = n0 + threadIdx.x*4;
    #pragma unroll
    for(int i=0;i<4;i++)
        #pragma unroll
        for(int j=0;j<4;j++)
            Cm[(size_t)(mm0+i)*Nd + nn0+j] = acc[i][j];
}

// ---------------- ADMM step kernels ----------------
// b = r_n + rho * AH(z - u)   out: g_b[b][c][n]
__global__ __launch_bounds__(256) void k_admm_b(const float* __restrict__ A,
                                                const float* __restrict__ r_n,
                                                const float* __restrict__ log_rho,
                                                const int* __restrict__ ns, int step){
    if(ns && step >= *ns) return;
    const float* __restrict__ Ar = A;
    const float* __restrict__ Ai = A + (size_t)Mq*Nq;
    int n0 = blockIdx.x*64, b0 = blockIdx.y*64;
    __shared__ float sVr[16][68], sVi[16][68];
    __shared__ float sAr[16][64], sAi[16][64];
    float accr[4][4]={}, acci[4][4]={};
    int t  = threadIdx.y*16 + threadIdx.x;
    int lr = t>>4, lc = t&15;
    int ar_r = t>>6, ar_c = t&63;
    for(int k=0;k<Mq;k+=16){
        #pragma unroll
        for(int jj=0;jj<4;jj++){
            int r = lr + (jj<<4); int bb = b0 + r;
            sVr[lc][r] = g_z[(size_t)bb*TMq +      (k+lc)] - g_u[(size_t)bb*TMq +      (k+lc)];
            sVi[lc][r] = g_z[(size_t)bb*TMq + Mq + (k+lc)] - g_u[(size_t)bb*TMq + Mq + (k+lc)];
            int mm = k + ar_r + jj*4;
            sAr[ar_r + jj*4][ar_c] = Ar[(size_t)mm*Nq + n0 + ar_c];
            sAi[ar_r + jj*4][ar_c] = Ai[(size_t)mm*Nq + n0 + ar_c];
        }
        __syncthreads();
        #pragma unroll
        for(int kk=0;kk<16;kk++){
            float vr_[4], vi_[4], ar_[4], ai_[4];
            *(float4*)vr_ = *(const float4*)&sVr[kk][threadIdx.y*4];
            *(float4*)vi_ = *(const float4*)&sVi[kk][threadIdx.y*4];
            *(float4*)ar_ = *(const float4*)&sAr[kk][threadIdx.x*4];
            *(float4*)ai_ = *(const float4*)&sAi[kk][threadIdx.x*4];
            #pragma unroll
            for(int i=0;i<4;i++)
                #pragma unroll
                for(int j=0;j<4;j++){
                    accr[i][j] += ar_[j]*vr_[i] + ai_[j]*vi_[i];
                    acci[i][j] += ar_[j]*vi_[i] - ai_[j]*vr_[i];
                }
        }
        __syncthreads();
    }
    float rho = load_rho(log_rho);
    int bb0 = b0 + threadIdx.y*4, nn0 = n0 + threadIdx.x*4;
    #pragma unroll
    for(int i=0;i<4;i++)
        #pragma unroll
        for(int j=0;j<4;j++){
            size_t idr = ((size_t)(bb0+i)*2 + 0)*Nq + nn0+j;
            size_t idi = ((size_t)(bb0+i)*2 + 1)*Nq + nn0+j;
            g_b[idr] = r_n[idr] + rho*accr[i][j];
            g_b[idi] = r_n[idi] + rho*acci[i][j];
        }
}

// Ab = Amv(b), split-K partials into g_part   out layout [b][p], p = m (real) / 512+m (imag)
__global__ __launch_bounds__(256) void k_admm_Ab(const float* __restrict__ A,
                                                 const int* __restrict__ ns, int step){
    if(ns && step >= *ns) return;
    const float* __restrict__ Ar = A;
    const float* __restrict__ Ai = A + (size_t)Mq*Nq;
    int m0 = blockIdx.x*64, b0 = blockIdx.y*64, ks = blockIdx.z;
    int k0 = ks*KSL;
    __shared__ float sBr[16][68], sBi[16][68], sAr[16][68], sAi[16][68];
    float accr[4][4]={}, acci[4][4]={};
    int t  = threadIdx.y*16 + threadIdx.x;
    int lr = t>>4, lc = t&15;
    for(int k=k0;k<k0+KSL;k+=16){
        #pragma unroll
        for(int jj=0;jj<4;jj++){
            int r = lr + (jj<<4);
            int bb = b0 + r;
            sBr[lc][r] = g_b[((size_t)bb*2+0)*Nq + k+lc];
            sBi[lc][r] = g_b[((size_t)bb*2+1)*Nq + k+lc];
            sAr[lc][r] = Ar[(size_t)(m0+r)*Nq + k+lc];
            sAi[lc][r] = Ai[(size_t)(m0+r)*Nq + k+lc];
        }
        __syncthreads();
        #pragma unroll
        for(int kk=0;kk<16;kk++){
            float br_[4], bi_[4], ar_[4], ai_[4];
            *(float4*)br_ = *(const float4*)&sBr[kk][threadIdx.y*4];
            *(float4*)bi_ = *(const float4*)&sBi[kk][threadIdx.y*4];
            *(float4*)ar_ = *(const float4*)&sAr[kk][threadIdx.x*4];
            *(float4*)ai_ = *(const float4*)&sAi[kk][threadIdx.x*4];
            #pragma unroll
            for(int i=0;i<4;i++)
                #pragma unroll
                for(int j=0;j<4;j++){
                    accr[i][j] += ar_[j]*br_[i] - ai_[j]*bi_[i];
                    acci[i][j] += ar_[j]*bi_[i] + ai_[j]*br_[i];
                }
        }
        __syncthreads();
    }
    int bb0 = b0 + threadIdx.y*4, mm0 = m0 + threadIdx.x*4;
    #pragma unroll
    for(int i=0;i<4;i++)
        #pragma unroll
        for(int j=0;j<4;j++){
            g_part[ks][(size_t)(bb0+i)*TMq +      mm0+j] = accr[i][j];
            g_part[ks][(size_t)(bb0+i)*TMq + Mq + mm0+j] = acci[i][j];
        }
}

__global__ void k_reduce_R(const int* __restrict__ ns, int step){
    if(ns && step >= *ns) return;
    int idx = blockIdx.x*256 + threadIdx.x;
    if(idx >= Bq*TMq) return;
    float s = 0.f;
    #pragma unroll
    for(int ks=0;ks<NSPLIT;ks++) s += g_part[ks][idx];
    g_R[idx] = s;
}
__global__ void k_reduce_Ax(const int* __restrict__ ns, int step){
    if(ns && step >= *ns) return;
    int idx = blockIdx.x*256 + threadIdx.x;
    if(idx >= Bq*TMq) return;
    float s = 0.f;
    #pragma unroll
    for(int ks=0;ks<NSPLIT;ks++) s += g_part[ks][idx];
    g_Ax[idx] = s;
}

// x_r = relu(b_r - real(AH(T)));  imag(x) = 0 (not stored)
__global__ __launch_bounds__(256) void k_admm_x(const float* __restrict__ A,
                                                const int* __restrict__ ns, int step){
    if(ns && step >= *ns) return;
    const float* __restrict__ Ar = A;
    const float* __restrict__ Ai = A + (size_t)Mq*Nq;
    int n0 = blockIdx.x*64, b0 = blockIdx.y*64;
    __shared__ float sTr[16][68], sTi[16][68];
    __shared__ float sAr[16][64], sAi[16][64];
    float acc[4][4] = {};
    int t  = threadIdx.y*16 + threadIdx.x;
    int lr = t>>4, lc = t&15;
    int ar_r = t>>6, ar_c = t&63;
    for(int k=0;k<Mq;k+=16){
        #pragma unroll
        for(int jj=0;jj<4;jj++){
            int r = lr + (jj<<4); int bb = b0 + r;
            sTr[lc][r] = g_Tm[(size_t)bb*TMq +      (k+lc)];
            sTi[lc][r] = g_Tm[(size_t)bb*TMq + Mq + (k+lc)];
            int mm = k + ar_r + jj*4;
            sAr[ar_r + jj*4][ar_c] = Ar[(size_t)mm*Nq + n0 + ar_c];
            sAi[ar_r + jj*4][ar_c] = Ai[(size_t)mm*Nq + n0 + ar_c];
        }
        __syncthreads();
        #pragma unroll
        for(int kk=0;kk<16;kk++){
            float tr_[4], ti_[4], ar_[4], ai_[4];
            *(float4*)tr_ = *(const float4*)&sTr[kk][threadIdx.y*4];
            *(float4*)ti_ = *(const float4*)&sTi[kk][threadIdx.y*4];
            *(float4*)ar_ = *(const float4*)&sAr[kk][threadIdx.x*4];
            *(float4*)ai_ = *(const float4*)&sAi[kk][threadIdx.x*4];
            #pragma unroll
            for(int i=0;i<4;i++)
                #pragma unroll
                for(int j=0;j<4;j++)
                    acc[i][j] += ar_[j]*tr_[i] + ai_[j]*ti_[i];
        }
        __syncthreads();
    }
    int bb0 = b0 + threadIdx.y*4, nn0 = n0 + threadIdx.x*4;
    #pragma unroll
    for(int i=0;i<4;i++)
        #pragma unroll
        for(int j=0;j<4;j++){
            size_t idr = ((size_t)(bb0+i)*2 + 0)*Nq + nn0+j;
            g_x[(size_t)(bb0+i)*Nq + nn0+j] = fmaxf(0.0f, g_b[idr] - acc[i][j]);
        }
}

// Ax = (Ar x_r, Ai x_r), split-K partials
__global__ __launch_bounds__(256) void k_admm_Ax(const float* __restrict__ A,
                                                 const int* __restrict__ ns, int step){
    if(ns && step >= *ns) return;
    const float* __restrict__ Ar = A;
    const float* __restrict__ Ai = A + (size_t)Mq*Nq;
    int m0 = blockIdx.x*64, b0 = blockIdx.y*64, ks = blockIdx.z;
    int k0 = ks*KSL;
    __shared__ float sXv[16][68], sAr[16][68], sAi[16][68];
    float accr[4][4]={}, acci[4][4]={};
    int t  = threadIdx.y*16 + threadIdx.x;
    int lr = t>>4, lc = t&15;
    for(int k=k0;k<k0+KSL;k+=16){
        #pragma unroll
        for(int jj=0;jj<4;jj++){
            int r = lr + (jj<<4);
            sXv[lc][r] = g_x[(size_t)(b0+r)*Nq + k+lc];
            sAr[lc][r] = Ar[(size_t)(m0+r)*Nq + k+lc];
            sAi[lc][r] = Ai[(size_t)(m0+r)*Nq + k+lc];
        }
        __syncthreads();
        #pragma unroll
        for(int kk=0;kk<16;kk++){
            float xv_[4], ar_[4], ai_[4];
            *(float4*)xv_ = *(const float4*)&sXv[kk][threadIdx.y*4];
            *(float4*)ar_ = *(const float4*)&sAr[kk][threadIdx.x*4];
            *(float4*)ai_ = *(const float4*)&sAi[kk][threadIdx.x*4];
            #pragma unroll
            for(int i=0;i<4;i++)
                #pragma unroll
                for(int j=0;j<4;j++){
                    accr[i][j] += ar_[j]*xv_[i];
                    acci[i][j] += ai_[j]*xv_[i];
                }
        }
        __syncthreads();
    }
    int bb0 = b0 + threadIdx.y*4, mm0 = m0 + threadIdx.x*4;
    #pragma unroll
    for(int i=0;i<4;i++)
        #pragma unroll
        for(int j=0;j<4;j++){
            g_part[ks][(size_t)(bb0+i)*TMq +      mm0+j] = accr[i][j];
            g_part[ks][(size_t)(bb0+i)*TMq + Mq + mm0+j] = acci[i][j];
        }
}

// d = Ax + u - y; nrm per batch; z = y + s*d; u = (1-s)*d
__global__ void k_admm_zu(const float* __restrict__ y,
                          const float* __restrict__ log_eps,
                          const int* __restrict__ ns, int step){
    if(ns && step >= *ns) return;
    int b = blockIdx.x;
    float d0[4]; float s = 0.f;
    #pragma unroll
    for(int j=0;j<4;j++){
        int p = threadIdx.x + 256*j;
        size_t q = (size_t)b*TMq + p;
        float d = g_Ax[q] + g_u[q] - y[q];
        d0[j] = d; s += d*d;
    }
    __shared__ float red[256];
    red[threadIdx.x] = s; __syncthreads();
    for(int o=128;o>0;o>>=1){ if(threadIdx.x<o) red[threadIdx.x]+=red[threadIdx.x+o]; __syncthreads(); }
    float nrm = sqrtf(red[0]);
    float eps = load_eps(log_eps);
    float scale = fminf(1.0f, eps/fmaxf(nrm, 1e-12f));
    #pragma unroll
    for(int j=0;j<4;j++){
        int p = threadIdx.x + 256*j;
        size_t q = (size_t)b*TMq + p;
        g_z[q] = y[q] + scale*d0[j];
        g_u[q] = (1.0f - scale)*d0[j];
    }
}

__global__ void k_init_zu(const float* __restrict__ y, const float* __restrict__ u_in){
    int idx = blockIdx.x*256 + threadIdx.x;
    if(idx < Bq*TMq){ g_z[idx] = y[idx]; g_u[idx] = u_in[idx]; }
}

__global__ void k_writeout(float* __restrict__ out){
    int idx = blockIdx.x*256 + threadIdx.x;
    const int xtot = Bq*2*Nq;
    const int total = xtot + Bq*TMq;
    if(idx >= total) return;
    if(idx < xtot){
        int b = idx / (2*Nq); int rem = idx - b*2*Nq;
        out[idx] = (rem < Nq) ? g_x[(size_t)b*Nq + rem] : 0.0f;
    }else{
        out[idx] = g_u[idx - xtot];
    }
}

// ---------------- host ----------------
extern "C" void kernel_launch(void* const* d_in, const int* in_sizes, int n_in,
                              void* d_out, int out_size){
    const float* r_n     = (const float*)d_in[0];
    const float* y       = (const float*)d_in[1];
    const float* u_in    = (const float*)d_in[2];
    const float* A       = (const float*)d_in[3];
    const float* log_rho = (const float*)d_in[4];
    const float* log_eps = (const float*)d_in[5];
    const int*   ns      = (n_in > 6) ? (const int*)d_in[6] : nullptr;

    static float *pS=nullptr,*pX=nullptr,*pT1=nullptr,*pT2=nullptr,*pR=nullptr,*pTm=nullptr;
    if(!pS){
        cudaGetSymbolAddress((void**)&pS,  g_S);
        cudaGetSymbolAddress((void**)&pX,  g_X);
        cudaGetSymbolAddress((void**)&pT1, g_T1);
        cudaGetSymbolAddress((void**)&pT2, g_T2);
        cudaGetSymbolAddress((void**)&pR,  g_R);
        cudaGetSymbolAddress((void**)&pTm, g_Tm);
    }

    dim3 blk(16,16);

    // S_block once
    k_S_partial<<<dim3(Mq/64, Mq/64, S_KSPLIT), blk>>>(A);
    k_S_combine<<<(Mq*Mq + 255)/256, 256>>>(log_rho);

    // lambda_max estimate
    k_pow_init<<<(TMq+255)/256, 256>>>();
    for(int i=0;i<12;i++){
        k_pow_mv<<<TMq, 256>>>();
        k_pow_norm<<<1, 1024>>>();
    }

    // Newton-Schulz inverse of S_block
    k_X_init<<<(TMq*TMq + 255)/256, 256>>>();
    for(int i=0;i<8;i++){
        k_gemm<<<dim3(TMq/64, TMq/64), blk>>>(pS, pX,  pT1, TMq, TMq, TMq, nullptr, 0);
        k_gemm<<<dim3(TMq/64, TMq/64), blk>>>(pX, pT1, pT2, TMq, TMq, TMq, nullptr, 0);
        k_newton_upd<<<(TMq*TMq + 255)/256, 256>>>();
    }

    // ADMM
    k_init_zu<<<(Bq*TMq + 255)/256, 256>>>(y, u_in);
    for(int step=0;step<5;step++){
        k_admm_b  <<<dim3(Nq/64, Bq/64),          blk>>>(A, r_n, log_rho, ns, step);
        k_admm_Ab <<<dim3(Mq/64, Bq/64, NSPLIT),  blk>>>(A, ns, step);
        k_reduce_R<<<(Bq*TMq + 255)/256, 256>>>(ns, step);
        k_gemm    <<<dim3(TMq/64, Bq/64),         blk>>>(pR, pX, pTm, Bq, TMq, TMq, ns, step);
        k_admm_x  <<<dim3(Nq/64, Bq/64),          blk>>>(A, ns, step);
        k_admm_Ax <<<dim3(Mq/64, Bq/64, NSPLIT),  blk>>>(A, ns, step);
        k_reduce_Ax<<<(Bq*TMq + 255)/256, 256>>>(ns, step);
        k_admm_zu <<<Bq, 256>>>(y, log_eps, ns, step);
    }

    k_writeout<<<(Bq*2*Nq + Bq*TMq + 255)/256, 256>>>((float*)d_out);
}

// round 6
// speedup vs baseline: 1.8236x; 1.8236x over previous
#include <cuda_runtime.h>
#include <cstdint>

#define Bq  256
#define Mq  512
#define Nq  8192
#define TMq 1024
#define NSPLIT 8
#define KSL (Nq/NSPLIT)      // 1024
#define S_KSPLIT 4
#define S_KSL (Nq/S_KSPLIT)  // 2048

// ---------------- device scratch (no allocations allowed) ----------------
__device__ float g_S  [TMq*TMq];
__device__ float g_X  [TMq*TMq];
__device__ float g_T1 [TMq*TMq];
__device__ float g_T2 [TMq*TMq];
__device__ float g_Spart[S_KSPLIT][2][Mq*Mq];
__device__ float g_Tm [Bq*TMq];     // w per step
__device__ float g_Arn[Bq*TMq];     // A @ r_n   (cat layout: [b][m] real, [b][512+m] imag)
__device__ float g_x  [Bq*Nq];
__device__ float g_z  [Bq*TMq];
__device__ float g_u  [Bq*TMq];
__device__ float g_part[NSPLIT][Bq*TMq];
__device__ float g_v[TMq];
__device__ float g_w[TMq];
__device__ float g_lam[1];

__device__ __forceinline__ float load_rho(const float* p){
    float v = *p; v = fminf(5.f, fmaxf(-5.f, v)); return expf(v);
}
__device__ __forceinline__ float load_eps(const float* p){
    float v = *p; v = fminf(0.f, fmaxf(-5.f, v)); return expf(v);
}

// ---------------- S = block([[Sr,-Si],[Si,Sr]]) precompute ----------------
__global__ __launch_bounds__(256) void k_S_partial(const float* __restrict__ A){
    const float* __restrict__ Ar = A;
    const float* __restrict__ Ai = A + (size_t)Mq*Nq;
    int j0 = blockIdx.x*64, i0 = blockIdx.y*64;
    int k0 = blockIdx.z*S_KSL;
    __shared__ float sRr[16][68], sRi[16][68], sCr[16][68], sCi[16][68];
    float rr[4][4]={}, ii_[4][4]={}, ir[4][4]={}, ri[4][4]={};
    int t  = threadIdx.y*16 + threadIdx.x;
    int lr = t>>4, lc = t&15;
    for(int k=k0;k<k0+S_KSL;k+=16){
        #pragma unroll
        for(int jj=0;jj<4;jj++){
            int r = lr + (jj<<4);
            sRr[lc][r] = Ar[(size_t)(i0+r)*Nq + (k+lc)];
            sRi[lc][r] = Ai[(size_t)(i0+r)*Nq + (k+lc)];
            sCr[lc][r] = Ar[(size_t)(j0+r)*Nq + (k+lc)];
            sCi[lc][r] = Ai[(size_t)(j0+r)*Nq + (k+lc)];
        }
        __syncthreads();
        #pragma unroll
        for(int kk=0;kk<16;kk++){
            float ar_[4], ai_[4], br_[4], bi_[4];
            *(float4*)ar_ = *(const float4*)&sRr[kk][threadIdx.y*4];
            *(float4*)ai_ = *(const float4*)&sRi[kk][threadIdx.y*4];
            *(float4*)br_ = *(const float4*)&sCr[kk][threadIdx.x*4];
            *(float4*)bi_ = *(const float4*)&sCi[kk][threadIdx.x*4];
            #pragma unroll
            for(int i=0;i<4;i++)
                #pragma unroll
                for(int j=0;j<4;j++){
                    rr [i][j] += ar_[i]*br_[j];
                    ii_[i][j] += ai_[i]*bi_[j];
                    ir [i][j] += ai_[i]*br_[j];
                    ri [i][j] += ar_[i]*bi_[j];
                }
        }
        __syncthreads();
    }
    int gi = i0 + threadIdx.y*4, gj = j0 + threadIdx.x*4;
    #pragma unroll
    for(int i=0;i<4;i++)
        #pragma unroll
        for(int j=0;j<4;j++){
            g_Spart[blockIdx.z][0][(size_t)(gi+i)*Mq + gj+j] = rr[i][j] + ii_[i][j];
            g_Spart[blockIdx.z][1][(size_t)(gi+i)*Mq + gj+j] = ir[i][j] - ri[i][j];
        }
}

__global__ void k_S_combine(const float* __restrict__ log_rho){
    int idx = blockIdx.x*256 + threadIdx.x;
    if(idx >= Mq*Mq) return;
    int i = idx/Mq, j = idx%Mq;
    float sr=0.f, si=0.f;
    #pragma unroll
    for(int ks=0;ks<S_KSPLIT;ks++){ sr += g_Spart[ks][0][idx]; si += g_Spart[ks][1][idx]; }
    float rho = load_rho(log_rho);
    if(i==j) sr += 1.0f/(rho + 1e-12f);
    g_S[(size_t) i     *TMq +      j] =  sr;
    g_S[(size_t) i     *TMq + Mq + j] = -si;
    g_S[(size_t)(Mq+i) *TMq +      j] =  si;
    g_S[(size_t)(Mq+i) *TMq + Mq + j] =  sr;
}

// ---------------- power iteration for lambda_max estimate ----------------
__global__ void k_pow_init(){
    int i = blockIdx.x*256 + threadIdx.x;
    if(i < TMq) g_v[i] = 1.0f + 0.001f*(float)i;
}
__global__ void k_pow_mv(){
    int row = blockIdx.x;
    float s = 0.f;
    for(int j=threadIdx.x;j<TMq;j+=256) s += g_S[(size_t)row*TMq + j]*g_v[j];
    __shared__ float red[256];
    red[threadIdx.x] = s; __syncthreads();
    for(int o=128;o>0;o>>=1){ if(threadIdx.x<o) red[threadIdx.x]+=red[threadIdx.x+o]; __syncthreads(); }
    if(threadIdx.x==0) g_w[row] = red[0];
}
__global__ void k_pow_norm(){
    __shared__ float red[1024];
    int tid = threadIdx.x;
    float w = g_w[tid];
    red[tid] = w*w; __syncthreads();
    for(int o=512;o>0;o>>=1){ if(tid<o) red[tid]+=red[tid+o]; __syncthreads(); }
    float nn = sqrtf(red[0]);
    g_v[tid] = g_w[tid]/nn;
    if(tid==0) g_lam[0] = nn;
}
// X0 = c*I with c = 2/(1.1*lam_max + 1/rho)  (spectrum of S lies in [1/rho, lam_max])
__global__ void k_X_init(const float* __restrict__ log_rho){
    int idx = blockIdx.x*256 + threadIdx.x;
    if(idx >= TMq*TMq) return;
    int i = idx/TMq, j = idx%TMq;
    float rho = load_rho(log_rho);
    float c = 2.0f/(1.1f*g_lam[0] + 1.0f/(rho + 1e-12f));
    g_X[idx] = (i==j) ? c : 0.0f;
}
__global__ void k_newton_upd(){
    int idx = blockIdx.x*256 + threadIdx.x;
    if(idx < TMq*TMq) g_X[idx] = 2.0f*g_X[idx] - g_T2[idx];
}

// ---------------- generic SGEMM: C[Md,Nd] = A[Md,Kd] @ B[Kd,Nd] ----------------
__global__ __launch_bounds__(256) void k_gemm(const float* __restrict__ Am,
                                              const float* __restrict__ Bm,
                                              float* __restrict__ Cm,
                                              int Md, int Nd, int Kd){
    int n0 = blockIdx.x*64, m0 = blockIdx.y*64;
    __shared__ float sA[16][68];
    __shared__ float sB[16][64];
    float acc[4][4] = {};
    int t  = threadIdx.y*16 + threadIdx.x;
    int lr = t>>4, lc = t&15;
    int br = t>>6, bc = t&63;
    for(int k=0;k<Kd;k+=16){
        #pragma unroll
        for(int jj=0;jj<4;jj++){
            int r = lr + (jj<<4);
            sA[lc][r] = Am[(size_t)(m0+r)*Kd + k + lc];
            sB[br + jj*4][bc] = Bm[(size_t)(k + br + jj*4)*Nd + n0 + bc];
        }
        __syncthreads();
        #pragma unroll
        for(int kk=0;kk<16;kk++){
            float a_[4], b_[4];
            *(float4*)a_ = *(const float4*)&sA[kk][threadIdx.y*4];
            *(float4*)b_ = *(const float4*)&sB[kk][threadIdx.x*4];
            #pragma unroll
            for(int i=0;i<4;i++)
                #pragma unroll
                for(int j=0;j<4;j++) acc[i][j] += a_[i]*b_[j];
        }
        __syncthreads();
    }
    int mm0 = m0 + threadIdx.y*4, nn0 = n0 + threadIdx.x*4;
    #pragma unroll
    for(int i=0;i<4;i++)
        #pragma unroll
        for(int j=0;j<4;j++)
            Cm[(size_t)(mm0+i)*Nd + nn0+j] = acc[i][j];
}

// ---------------- Amv (complex) with split-K into g_part ----------------
// src is (B,2,N) complex; out partials [b][m]/[b][512+m]
__global__ __launch_bounds__(256) void k_Amv(const float* __restrict__ A,
                                             const float* __restrict__ src){
    const float* __restrict__ Ar = A;
    const float* __restrict__ Ai = A + (size_t)Mq*Nq;
    int m0 = blockIdx.x*64, b0 = blockIdx.y*64, ks = blockIdx.z;
    int k0 = ks*KSL;
    __shared__ float sBr[16][68], sBi[16][68], sAr[16][68], sAi[16][68];
    float accr[4][4]={}, acci[4][4]={};
    int t  = threadIdx.y*16 + threadIdx.x;
    int lr = t>>4, lc = t&15;
    for(int k=k0;k<k0+KSL;k+=16){
        #pragma unroll
        for(int jj=0;jj<4;jj++){
            int r = lr + (jj<<4);
            int bb = b0 + r;
            sBr[lc][r] = src[((size_t)bb*2+0)*Nq + k+lc];
            sBi[lc][r] = src[((size_t)bb*2+1)*Nq + k+lc];
            sAr[lc][r] = Ar[(size_t)(m0+r)*Nq + k+lc];
            sAi[lc][r] = Ai[(size_t)(m0+r)*Nq + k+lc];
        }
        __syncthreads();
        #pragma unroll
        for(int kk=0;kk<16;kk++){
            float br_[4], bi_[4], ar_[4], ai_[4];
            *(float4*)br_ = *(const float4*)&sBr[kk][threadIdx.y*4];
            *(float4*)bi_ = *(const float4*)&sBi[kk][threadIdx.y*4];
            *(float4*)ar_ = *(const float4*)&sAr[kk][threadIdx.x*4];
            *(float4*)ai_ = *(const float4*)&sAi[kk][threadIdx.x*4];
            #pragma unroll
            for(int i=0;i<4;i++)
                #pragma unroll
                for(int j=0;j<4;j++){
                    accr[i][j] += ar_[j]*br_[i] - ai_[j]*bi_[i];
                    acci[i][j] += ar_[j]*bi_[i] + ai_[j]*br_[i];
                }
        }
        __syncthreads();
    }
    int bb0 = b0 + threadIdx.y*4, mm0 = m0 + threadIdx.x*4;
    #pragma unroll
    for(int i=0;i<4;i++)
        #pragma unroll
        for(int j=0;j<4;j++){
            g_part[ks][(size_t)(bb0+i)*TMq +      mm0+j] = accr[i][j];
            g_part[ks][(size_t)(bb0+i)*TMq + Mq + mm0+j] = acci[i][j];
        }
}

__global__ void k_reduce(float* __restrict__ dst){
    int idx = blockIdx.x*256 + threadIdx.x;
    if(idx >= Bq*TMq) return;
    float s = 0.f;
    #pragma unroll
    for(int ks=0;ks<NSPLIT;ks++) s += g_part[ks][idx];
    dst[idx] = s;
}

// ---------------- per-step: w = ((z-u) - Arn) @ X  ->  g_Tm ----------------
__global__ __launch_bounds__(256) void k_w_gemm(const int* __restrict__ ns, int step){
    if(ns && step >= *ns) return;
    int n0 = blockIdx.x*64, m0 = blockIdx.y*64;   // m = batch
    __shared__ float sA[16][68];
    __shared__ float sB[16][64];
    float acc[4][4] = {};
    int t  = threadIdx.y*16 + threadIdx.x;
    int lr = t>>4, lc = t&15;
    int br = t>>6, bc = t&63;
    for(int k=0;k<TMq;k+=16){
        #pragma unroll
        for(int jj=0;jj<4;jj++){
            int r = lr + (jj<<4);
            size_t vi = (size_t)(m0+r)*TMq + k + lc;
            sA[lc][r] = g_z[vi] - g_u[vi] - g_Arn[vi];
            sB[br + jj*4][bc] = g_X[(size_t)(k + br + jj*4)*TMq + n0 + bc];
        }
        __syncthreads();
        #pragma unroll
        for(int kk=0;kk<16;kk++){
            float a_[4], b_[4];
            *(float4*)a_ = *(const float4*)&sA[kk][threadIdx.y*4];
            *(float4*)b_ = *(const float4*)&sB[kk][threadIdx.x*4];
            #pragma unroll
            for(int i=0;i<4;i++)
                #pragma unroll
                for(int j=0;j<4;j++) acc[i][j] += a_[i]*b_[j];
        }
        __syncthreads();
    }
    int mm0 = m0 + threadIdx.y*4, nn0 = n0 + threadIdx.x*4;
    #pragma unroll
    for(int i=0;i<4;i++)
        #pragma unroll
        for(int j=0;j<4;j++)
            g_Tm[(size_t)(mm0+i)*TMq + nn0+j] = acc[i][j];
}

// ---------------- x = relu(r_n_r + Ar^T w_r + Ai^T w_i) ----------------
__global__ __launch_bounds__(256) void k_admm_x(const float* __restrict__ A,
                                                const float* __restrict__ r_n,
                                                const int* __restrict__ ns, int step){
    if(ns && step >= *ns) return;
    const float* __restrict__ Ar = A;
    const float* __restrict__ Ai = A + (size_t)Mq*Nq;
    int n0 = blockIdx.x*64, b0 = blockIdx.y*64;
    __shared__ float sTr[16][68], sTi[16][68];
    __shared__ float sAr[16][64], sAi[16][64];
    float acc[4][4] = {};
    int t  = threadIdx.y*16 + threadIdx.x;
    int lr = t>>4, lc = t&15;
    int ar_r = t>>6, ar_c = t&63;
    for(int k=0;k<Mq;k+=16){
        #pragma unroll
        for(int jj=0;jj<4;jj++){
            int r = lr + (jj<<4); int bb = b0 + r;
            sTr[lc][r] = g_Tm[(size_t)bb*TMq +      (k+lc)];
            sTi[lc][r] = g_Tm[(size_t)bb*TMq + Mq + (k+lc)];
            int mm = k + ar_r + jj*4;
            sAr[ar_r + jj*4][ar_c] = Ar[(size_t)mm*Nq + n0 + ar_c];
            sAi[ar_r + jj*4][ar_c] = Ai[(size_t)mm*Nq + n0 + ar_c];
        }
        __syncthreads();
        #pragma unroll
        for(int kk=0;kk<16;kk++){
            float tr_[4], ti_[4], ar_[4], ai_[4];
            *(float4*)tr_ = *(const float4*)&sTr[kk][threadIdx.y*4];
            *(float4*)ti_ = *(const float4*)&sTi[kk][threadIdx.y*4];
            *(float4*)ar_ = *(const float4*)&sAr[kk][threadIdx.x*4];
            *(float4*)ai_ = *(const float4*)&sAi[kk][threadIdx.x*4];
            #pragma unroll
            for(int i=0;i<4;i++)
                #pragma unroll
                for(int j=0;j<4;j++)
                    acc[i][j] += ar_[j]*tr_[i] + ai_[j]*ti_[i];
        }
        __syncthreads();
    }
    int bb0 = b0 + threadIdx.y*4, nn0 = n0 + threadIdx.x*4;
    #pragma unroll
    for(int i=0;i<4;i++)
        #pragma unroll
        for(int j=0;j<4;j++){
            size_t idr = ((size_t)(bb0+i)*2 + 0)*Nq + nn0+j;
            g_x[(size_t)(bb0+i)*Nq + nn0+j] = fmaxf(0.0f, r_n[idr] + acc[i][j]);
        }
}

// ---------------- Ax = (Ar x, Ai x), split-K partials ----------------
__global__ __launch_bounds__(256) void k_admm_Ax(const float* __restrict__ A,
                                                 const int* __restrict__ ns, int step){
    if(ns && step >= *ns) return;
    const float* __restrict__ Ar = A;
    const float* __restrict__ Ai = A + (size_t)Mq*Nq;
    int m0 = blockIdx.x*64, b0 = blockIdx.y*64, ks = blockIdx.z;
    int k0 = ks*KSL;
    __shared__ float sXv[16][68], sAr[16][68], sAi[16][68];
    float accr[4][4]={}, acci[4][4]={};
    int t  = threadIdx.y*16 + threadIdx.x;
    int lr = t>>4, lc = t&15;
    for(int k=k0;k<k0+KSL;k+=16){
        #pragma unroll
        for(int jj=0;jj<4;jj++){
            int r = lr + (jj<<4);
            sXv[lc][r] = g_x[(size_t)(b0+r)*Nq + k+lc];
            sAr[lc][r] = Ar[(size_t)(m0+r)*Nq + k+lc];
            sAi[lc][r] = Ai[(size_t)(m0+r)*Nq + k+lc];
        }
        __syncthreads();
        #pragma unroll
        for(int kk=0;kk<16;kk++){
            float xv_[4], ar_[4], ai_[4];
            *(float4*)xv_ = *(const float4*)&sXv[kk][threadIdx.y*4];
            *(float4*)ar_ = *(const float4*)&sAr[kk][threadIdx.x*4];
            *(float4*)ai_ = *(const float4*)&sAi[kk][threadIdx.x*4];
            #pragma unroll
            for(int i=0;i<4;i++)
                #pragma unroll
                for(int j=0;j<4;j++){
                    accr[i][j] += ar_[j]*xv_[i];
                    acci[i][j] += ai_[j]*xv_[i];
                }
        }
        __syncthreads();
    }
    int bb0 = b0 + threadIdx.y*4, mm0 = m0 + threadIdx.x*4;
    #pragma unroll
    for(int i=0;i<4;i++)
        #pragma unroll
        for(int j=0;j<4;j++){
            g_part[ks][(size_t)(bb0+i)*TMq +      mm0+j] = accr[i][j];
            g_part[ks][(size_t)(bb0+i)*TMq + Mq + mm0+j] = acci[i][j];
        }
}

// d = Ax + u - y (Ax summed from partials inline); z = y + s*d; u = (1-s)*d
__global__ void k_admm_zu(const float* __restrict__ y,
                          const float* __restrict__ log_eps,
                          const int* __restrict__ ns, int step){
    if(ns && step >= *ns) return;
    int b = blockIdx.x;
    float d0[4]; float s = 0.f;
    #pragma unroll
    for(int j=0;j<4;j++){
        int p = threadIdx.x + 256*j;
        size_t q = (size_t)b*TMq + p;
        float ax = 0.f;
        #pragma unroll
        for(int ks=0;ks<NSPLIT;ks++) ax += g_part[ks][q];
        float d = ax + g_u[q] - y[q];
        d0[j] = d; s += d*d;
    }
    __shared__ float red[256];
    red[threadIdx.x] = s; __syncthreads();
    for(int o=128;o>0;o>>=1){ if(threadIdx.x<o) red[threadIdx.x]+=red[threadIdx.x+o]; __syncthreads(); }
    float nrm = sqrtf(red[0]);
    float eps = load_eps(log_eps);
    float scale = fminf(1.0f, eps/fmaxf(nrm, 1e-12f));
    #pragma unroll
    for(int j=0;j<4;j++){
        int p = threadIdx.x + 256*j;
        size_t q = (size_t)b*TMq + p;
        g_z[q] = y[q] + scale*d0[j];
        g_u[q] = (1.0f - scale)*d0[j];
    }
}

__global__ void k_init_zu(const float* __restrict__ y, const float* __restrict__ u_in){
    int idx = blockIdx.x*256 + threadIdx.x;
    if(idx < Bq*TMq){ g_z[idx] = y[idx]; g_u[idx] = u_in[idx]; }
}

__global__ void k_writeout(float* __restrict__ out){
    int idx = blockIdx.x*256 + threadIdx.x;
    const int xtot = Bq*2*Nq;
    const int total = xtot + Bq*TMq;
    if(idx >= total) return;
    if(idx < xtot){
        int b = idx / (2*Nq); int rem = idx - b*2*Nq;
        out[idx] = (rem < Nq) ? g_x[(size_t)b*Nq + rem] : 0.0f;
    }else{
        out[idx] = g_u[idx - xtot];
    }
}

// ---------------- host ----------------
extern "C" void kernel_launch(void* const* d_in, const int* in_sizes, int n_in,
                              void* d_out, int out_size){
    const float* r_n     = (const float*)d_in[0];
    const float* y       = (const float*)d_in[1];
    const float* u_in    = (const float*)d_in[2];
    const float* A       = (const float*)d_in[3];
    const float* log_rho = (const float*)d_in[4];
    const float* log_eps = (const float*)d_in[5];
    const int*   ns      = (n_in > 6) ? (const int*)d_in[6] : nullptr;

    static float *pS=nullptr,*pX=nullptr,*pT1=nullptr,*pT2=nullptr,*pArn=nullptr;
    if(!pS){
        cudaGetSymbolAddress((void**)&pS,   g_S);
        cudaGetSymbolAddress((void**)&pX,   g_X);
        cudaGetSymbolAddress((void**)&pT1,  g_T1);
        cudaGetSymbolAddress((void**)&pT2,  g_T2);
        cudaGetSymbolAddress((void**)&pArn, g_Arn);
    }

    dim3 blk(16,16);

    // S_block once
    k_S_partial<<<dim3(Mq/64, Mq/64, S_KSPLIT), blk>>>(A);
    k_S_combine<<<(Mq*Mq + 255)/256, 256>>>(log_rho);

    // lambda_max estimate
    k_pow_init<<<(TMq+255)/256, 256>>>();
    for(int i=0;i<10;i++){
        k_pow_mv<<<TMq, 256>>>();
        k_pow_norm<<<1, 1024>>>();
    }

    // Newton-Schulz inverse of S_block (6 iters; c = 2/(1.1*lam + 1/rho) init)
    k_X_init<<<(TMq*TMq + 255)/256, 256>>>(log_rho);
    for(int i=0;i<6;i++){
        k_gemm<<<dim3(TMq/64, TMq/64), blk>>>(pS, pX,  pT1, TMq, TMq, TMq);
        k_gemm<<<dim3(TMq/64, TMq/64), blk>>>(pX, pT1, pT2, TMq, TMq, TMq);
        k_newton_upd<<<(TMq*TMq + 255)/256, 256>>>();
    }

    // Arn = A @ r_n  (once)
    k_Amv<<<dim3(Mq/64, Bq/64, NSPLIT), blk>>>(A, r_n);
    k_reduce<<<(Bq*TMq + 255)/256, 256>>>(pArn);

    // ADMM loop:  w = ((z-u) - Arn) @ X ;  x = relu(r_n + AH(w)) ;  Ax ;  z/u update
    k_init_zu<<<(Bq*TMq + 255)/256, 256>>>(y, u_in);
    for(int step=0;step<5;step++){
        k_w_gemm <<<dim3(TMq/64, Bq/64),         blk>>>(ns, step);
        k_admm_x <<<dim3(Nq/64, Bq/64),          blk>>>(A, r_n, ns, step);
        k_admm_Ax<<<dim3(Mq/64, Bq/64, NSPLIT),  blk>>>(A, ns, step);
        k_admm_zu<<<Bq, 256>>>(y, log_eps, ns, step);
    }

    k_writeout<<<(Bq*2*Nq + Bq*TMq + 255)/256, 256>>>((float*)d_out);
}

// round 7
// speedup vs baseline: 1.9628x; 1.0764x over previous
#include <cuda_runtime.h>
#include <cstdint>

#define Bq  256
#define Mq  512
#define Nq  8192
#define TMq 1024
#define NSPLIT 8
#define S_KSPLIT 4

// mma tile config
#define BM 128
#define BN 64
#define BKt 16
#define LDK 20   // BKt + 4 pad

// ---------------- device scratch (no allocations allowed) ----------------
__device__ float g_S  [TMq*TMq];
__device__ float g_X  [TMq*TMq];
__device__ float g_T1 [TMq*TMq];
__device__ float g_T2 [TMq*TMq];
__device__ float g_SpartP[S_KSPLIT][TMq*Mq];   // rows 0..511 = Sr, 512..1023 = Si
__device__ float g_Tm [Bq*TMq];     // w per step
__device__ float g_Arn[Bq*TMq];     // A @ r_n  (cat layout [b][m] real, [b][512+m] imag)
__device__ float g_x  [Bq*Nq];
__device__ float g_z  [Bq*TMq];
__device__ float g_u  [Bq*TMq];
__device__ float g_part[NSPLIT][Bq*TMq];
__device__ float g_v[TMq];
__device__ float g_w[TMq];
__device__ float g_lam[1];

__device__ __forceinline__ float load_rho(const float* p){
    float v = *p; v = fminf(5.f, fmaxf(-5.f, v)); return expf(v);
}
__device__ __forceinline__ float load_eps(const float* p){
    float v = *p; v = fminf(0.f, fmaxf(-5.f, v)); return expf(v);
}

// ---------------- tf32 helpers ----------------
__device__ __forceinline__ uint32_t f2tf(float v){
    uint32_t r; asm("cvt.rna.tf32.f32 %0, %1;" : "=r"(r) : "f"(v)); return r;
}
__device__ __forceinline__ void split4_store(float4 v, float* ph, float* pl){
    float hx = __uint_as_float(f2tf(v.x));
    float hy = __uint_as_float(f2tf(v.y));
    float hz = __uint_as_float(f2tf(v.z));
    float hw = __uint_as_float(f2tf(v.w));
    *(float4*)ph = make_float4(hx,hy,hz,hw);
    *(float4*)pl = make_float4(
        __uint_as_float(f2tf(v.x-hx)), __uint_as_float(f2tf(v.y-hy)),
        __uint_as_float(f2tf(v.z-hz)), __uint_as_float(f2tf(v.w-hw)));
}
__device__ __forceinline__ void mma8(float* c, const uint32_t* a, const uint32_t* b){
    asm volatile("mma.sync.aligned.m16n8k8.row.col.f32.tf32.tf32.f32 "
        "{%0,%1,%2,%3}, {%4,%5,%6,%7}, {%8,%9}, {%0,%1,%2,%3};\n"
        : "+f"(c[0]),"+f"(c[1]),"+f"(c[2]),"+f"(c[3])
        : "r"(a[0]),"r"(a[1]),"r"(a[2]),"r"(a[3]), "r"(b[0]),"r"(b[1]));
}

// common per-kernel prolog: shared tiles + warp/lane coords + accumulators
#define MMA_PROLOG() \
    __shared__ float sAh[BM][LDK], sAl[BM][LDK], sBh[BN][LDK], sBl[BN][LDK]; \
    float acc[2][4][4] = {}; \
    const int tid = threadIdx.x; const int lane = tid & 31; const int wid = tid >> 5; \
    const int wm = wid & 3; const int wn = wid >> 2; \
    const int qr = lane >> 2; const int qc = lane & 3; \
    (void)qr; (void)qc;

// one BK=16 stage of 3xTF32 mma on the staged tiles
#define MMA_COMPUTE() do{ \
  _Pragma("unroll") \
  for(int k8=0;k8<BKt;k8+=8){ \
    uint32_t ah[2][4], al[2][4], bh[4][2], bl[4][2]; \
    _Pragma("unroll") for(int mt=0;mt<2;mt++){ \
      int m = wm*32 + mt*16; \
      ah[mt][0]=__float_as_uint(sAh[m+qr  ][k8+qc  ]); al[mt][0]=__float_as_uint(sAl[m+qr  ][k8+qc  ]); \
      ah[mt][1]=__float_as_uint(sAh[m+qr+8][k8+qc  ]); al[mt][1]=__float_as_uint(sAl[m+qr+8][k8+qc  ]); \
      ah[mt][2]=__float_as_uint(sAh[m+qr  ][k8+qc+4]); al[mt][2]=__float_as_uint(sAl[m+qr  ][k8+qc+4]); \
      ah[mt][3]=__float_as_uint(sAh[m+qr+8][k8+qc+4]); al[mt][3]=__float_as_uint(sAl[m+qr+8][k8+qc+4]); \
    } \
    _Pragma("unroll") for(int nt=0;nt<4;nt++){ \
      int n = wn*32 + nt*8; \
      bh[nt][0]=__float_as_uint(sBh[n+qr][k8+qc  ]); bl[nt][0]=__float_as_uint(sBl[n+qr][k8+qc  ]); \
      bh[nt][1]=__float_as_uint(sBh[n+qr][k8+qc+4]); bl[nt][1]=__float_as_uint(sBl[n+qr][k8+qc+4]); \
    } \
    _Pragma("unroll") for(int mt=0;mt<2;mt++) \
      _Pragma("unroll") for(int nt=0;nt<4;nt++){ \
        mma8(acc[mt][nt], ah[mt], bh[nt]); \
        mma8(acc[mt][nt], ah[mt], bl[nt]); \
        mma8(acc[mt][nt], al[mt], bh[nt]); \
      } \
  } \
}while(0)

#define MMA_EPILOG(STMT) \
  _Pragma("unroll") for(int mt=0;mt<2;mt++) \
  _Pragma("unroll") for(int nt=0;nt<4;nt++) \
  _Pragma("unroll") for(int ci=0;ci<4;ci++){ \
      int m = m0 + wm*32 + mt*16 + qr + ((ci>>1)<<3); \
      int n = n0 + wn*32 + nt*8 + (qc<<1) + (ci&1); \
      float v = acc[mt][nt][ci]; \
      STMT; \
  }

// direct K-major loaders (row-major source with K contiguous)
#define LOAD_A_DIRECT(PA, LD) do{ \
  _Pragma("unroll") for(int i_=0;i_<2;i_++){ \
    int idx_ = tid + i_*256; int m_ = idx_ >> 2; int kq_ = (idx_ & 3) << 2; \
    float4 v_ = *(const float4*)&(PA)[(size_t)(m0+m_)*(LD) + k0 + kq_]; \
    split4_store(v_, &sAh[m_][kq_], &sAl[m_][kq_]); \
  } \
}while(0)

#define LOAD_B_DIRECT(PB, LD) do{ \
    int n_ = tid >> 2; int kq_ = (tid & 3) << 2; \
    float4 v_ = *(const float4*)&(PB)[(size_t)(n0+n_)*(LD) + k0 + kq_]; \
    split4_store(v_, &sBh[n_][kq_], &sBl[n_][kq_]); \
}while(0)

// ---------------- S precompute: P = [Sr; Si] (1024 x 512), split-K over 2N ----------------
// Sr[i][j] = <[Ar_i,Ai_i],[Ar_j,Ai_j]> ; Si[i][j] = <[Ai_i,-Ar_i],[Ar_j,Ai_j]>
__global__ __launch_bounds__(256) void k_S_partial_mma(const float* __restrict__ A){
    MMA_PROLOG();
    const int n0 = blockIdx.x*BN, m0 = blockIdx.y*BM;
    const int kbeg = blockIdx.z*(2*Nq/S_KSPLIT), kend = kbeg + 2*Nq/S_KSPLIT;
    for(int k0=kbeg;k0<kend;k0+=BKt){
        bool second = (k0 >= Nq);
        #pragma unroll
        for(int i_=0;i_<2;i_++){
            int idx_ = tid + i_*256; int m_ = idx_ >> 2; int kq_ = (idx_ & 3) << 2;
            int i2 = m0 + m_;
            const float* p_; float sgn = 1.f;
            if(!second) p_ = A + (size_t)i2*Nq + k0 + kq_;
            else { p_ = A + (size_t)(i2^512)*Nq + (k0 - Nq) + kq_; if(i2 >= 512) sgn = -1.f; }
            float4 v_ = *(const float4*)p_;
            v_.x*=sgn; v_.y*=sgn; v_.z*=sgn; v_.w*=sgn;
            split4_store(v_, &sAh[m_][kq_], &sAl[m_][kq_]);
        }
        {
            int n_ = tid >> 2; int kq_ = (tid & 3) << 2;
            int j = n0 + n_;
            const float* p_ = second ? (A + (size_t)(j+512)*Nq + (k0 - Nq) + kq_)
                                     : (A + (size_t)j*Nq + k0 + kq_);
            float4 v_ = *(const float4*)p_;
            split4_store(v_, &sBh[n_][kq_], &sBl[n_][kq_]);
        }
        __syncthreads();
        MMA_COMPUTE();
        __syncthreads();
    }
    MMA_EPILOG( g_SpartP[blockIdx.z][(size_t)m*Mq + n] = v; )
}

__global__ void k_S_combine(const float* __restrict__ log_rho){
    int idx = blockIdx.x*256 + threadIdx.x;
    if(idx >= Mq*Mq) return;
    int i = idx/Mq, j = idx%Mq;
    float sr=0.f, si=0.f;
    #pragma unroll
    for(int ks=0;ks<S_KSPLIT;ks++){
        sr += g_SpartP[ks][(size_t)i*Mq + j];
        si += g_SpartP[ks][(size_t)(Mq+i)*Mq + j];
    }
    float rho = load_rho(log_rho);
    if(i==j) sr += 1.0f/(rho + 1e-12f);
    g_S[(size_t) i     *TMq +      j] =  sr;
    g_S[(size_t) i     *TMq + Mq + j] = -si;
    g_S[(size_t)(Mq+i) *TMq +      j] =  si;
    g_S[(size_t)(Mq+i) *TMq + Mq + j] =  sr;
}

// ---------------- power iteration for lambda_max estimate ----------------
__global__ void k_pow_init(){
    int i = blockIdx.x*256 + threadIdx.x;
    if(i < TMq) g_v[i] = 1.0f + 0.001f*(float)i;
}
__global__ void k_pow_mv(){
    int row = blockIdx.x;
    float s = 0.f;
    for(int j=threadIdx.x;j<TMq;j+=256) s += g_S[(size_t)row*TMq + j]*g_v[j];
    __shared__ float red[256];
    red[threadIdx.x] = s; __syncthreads();
    for(int o=128;o>0;o>>=1){ if(threadIdx.x<o) red[threadIdx.x]+=red[threadIdx.x+o]; __syncthreads(); }
    if(threadIdx.x==0) g_w[row] = red[0];
}
__global__ void k_pow_norm(){
    __shared__ float red[1024];
    int tid = threadIdx.x;
    float w = g_w[tid];
    red[tid] = w*w; __syncthreads();
    for(int o=512;o>0;o>>=1){ if(tid<o) red[tid]+=red[tid+o]; __syncthreads(); }
    float nn = sqrtf(red[0]);
    g_v[tid] = g_w[tid]/nn;
    if(tid==0) g_lam[0] = nn;
}
__global__ void k_X_init(const float* __restrict__ log_rho){
    int idx = blockIdx.x*256 + threadIdx.x;
    if(idx >= TMq*TMq) return;
    int i = idx/TMq, j = idx%TMq;
    float rho = load_rho(log_rho);
    float c = 2.0f/(1.1f*g_lam[0] + 1.0f/(rho + 1e-12f));
    g_X[idx] = (i==j) ? c : 0.0f;
}
// X = 2X - (T2 + T2^T)/2  (symmetrize so symmetric-reads of X are exact)
__global__ void k_newton_upd(){
    int idx = blockIdx.x*256 + threadIdx.x;
    if(idx >= TMq*TMq) return;
    int i = idx/TMq, j = idx%TMq;
    g_X[idx] = 2.0f*g_X[idx] - 0.5f*(g_T2[idx] + g_T2[(size_t)j*TMq + i]);
}

// ---------------- Newton GEMM: C = A @ B, B symmetric (read [n][k]) ----------------
__global__ __launch_bounds__(256) void k_gemm_mma(const float* __restrict__ Am,
                                                  const float* __restrict__ Bm,
                                                  float* __restrict__ Cm){
    MMA_PROLOG();
    const int n0 = blockIdx.x*BN, m0 = blockIdx.y*BM;
    for(int k0=0;k0<TMq;k0+=BKt){
        LOAD_A_DIRECT(Am, TMq);
        LOAD_B_DIRECT(Bm, TMq);
        __syncthreads();
        MMA_COMPUTE();
        __syncthreads();
    }
    MMA_EPILOG( Cm[(size_t)m*TMq + n] = v; )
}

// ---------------- Arn = Amv(r_n): C[b][p], K = 2N doubled, split-K ----------------
__global__ __launch_bounds__(256) void k_Amv_mma(const float* __restrict__ A,
                                                 const float* __restrict__ src){
    MMA_PROLOG();
    const int n0 = blockIdx.x*BN, m0 = blockIdx.y*BM;
    const int kbeg = blockIdx.z*(2*Nq/NSPLIT), kend = kbeg + 2*Nq/NSPLIT;
    for(int k0=kbeg;k0<kend;k0+=BKt){
        bool second = (k0 >= Nq);
        LOAD_A_DIRECT(src, 2*Nq);
        {
            int n_ = tid >> 2; int kq_ = (tid & 3) << 2;
            int p = n0 + n_;
            const float* p_; float sgn = 1.f;
            if(!second) p_ = A + (size_t)p*Nq + k0 + kq_;
            else { p_ = A + (size_t)(p^512)*Nq + (k0 - Nq) + kq_; if(p < 512) sgn = -1.f; }
            float4 v_ = *(const float4*)p_;
            v_.x*=sgn; v_.y*=sgn; v_.z*=sgn; v_.w*=sgn;
            split4_store(v_, &sBh[n_][kq_], &sBl[n_][kq_]);
        }
        __syncthreads();
        MMA_COMPUTE();
        __syncthreads();
    }
    MMA_EPILOG( g_part[blockIdx.z][(size_t)m*TMq + n] = v; )
}

__global__ void k_reduce(float* __restrict__ dst){
    int idx = blockIdx.x*256 + threadIdx.x;
    if(idx >= Bq*TMq) return;
    float s = 0.f;
    #pragma unroll
    for(int ks=0;ks<NSPLIT;ks++) s += g_part[ks][idx];
    dst[idx] = s;
}

// ---------------- w = ((z-u) - Arn) @ X ----------------
__global__ __launch_bounds__(256) void k_w_gemm_mma(const int* __restrict__ ns, int step){
    if(ns && step >= *ns) return;
    MMA_PROLOG();
    const int n0 = blockIdx.x*BN, m0 = blockIdx.y*BM;
    for(int k0=0;k0<TMq;k0+=BKt){
        #pragma unroll
        for(int i_=0;i_<2;i_++){
            int idx_ = tid + i_*256; int m_ = idx_ >> 2; int kq_ = (idx_ & 3) << 2;
            size_t off = (size_t)(m0+m_)*TMq + k0 + kq_;
            float4 a_ = *(const float4*)&g_z[off];
            float4 b_ = *(const float4*)&g_u[off];
            float4 c_ = *(const float4*)&g_Arn[off];
            float4 v_ = make_float4(a_.x-b_.x-c_.x, a_.y-b_.y-c_.y, a_.z-b_.z-c_.z, a_.w-b_.w-c_.w);
            split4_store(v_, &sAh[m_][kq_], &sAl[m_][kq_]);
        }
        LOAD_B_DIRECT(g_X, TMq);   // X symmetric
        __syncthreads();
        MMA_COMPUTE();
        __syncthreads();
    }
    MMA_EPILOG( g_Tm[(size_t)m*TMq + n] = v; )
}

// ---------------- x = relu(r_n_r + AH(w)_r): C[b][n], B-op = A^T (transpose load) ----------------
__global__ __launch_bounds__(256) void k_admm_x_mma(const float* __restrict__ A,
                                                    const float* __restrict__ r_n,
                                                    const int* __restrict__ ns, int step){
    if(ns && step >= *ns) return;
    MMA_PROLOG();
    const int n0 = blockIdx.x*BN, m0 = blockIdx.y*BM;
    for(int k0=0;k0<TMq;k0+=BKt){
        LOAD_A_DIRECT(g_Tm, TMq);
        {
            int kk_ = tid >> 4; int nq_ = (tid & 15) << 2;
            float4 v_ = *(const float4*)&A[(size_t)(k0+kk_)*Nq + n0 + nq_];
            float h0 = __uint_as_float(f2tf(v_.x)); float h1 = __uint_as_float(f2tf(v_.y));
            float h2 = __uint_as_float(f2tf(v_.z)); float h3 = __uint_as_float(f2tf(v_.w));
            sBh[nq_+0][kk_] = h0; sBl[nq_+0][kk_] = __uint_as_float(f2tf(v_.x-h0));
            sBh[nq_+1][kk_] = h1; sBl[nq_+1][kk_] = __uint_as_float(f2tf(v_.y-h1));
            sBh[nq_+2][kk_] = h2; sBl[nq_+2][kk_] = __uint_as_float(f2tf(v_.z-h2));
            sBh[nq_+3][kk_] = h3; sBl[nq_+3][kk_] = __uint_as_float(f2tf(v_.w-h3));
        }
        __syncthreads();
        MMA_COMPUTE();
        __syncthreads();
    }
    MMA_EPILOG( g_x[(size_t)m*Nq + n] = fmaxf(0.0f, r_n[(size_t)m*2*Nq + n] + v); )
}

// ---------------- Ax: C[b][p] = x @ A_row_p, split-K over N ----------------
__global__ __launch_bounds__(256) void k_admm_Ax_mma(const float* __restrict__ A,
                                                     const int* __restrict__ ns, int step){
    if(ns && step >= *ns) return;
    MMA_PROLOG();
    const int n0 = blockIdx.x*BN, m0 = blockIdx.y*BM;
    const int kbeg = blockIdx.z*(Nq/NSPLIT), kend = kbeg + Nq/NSPLIT;
    for(int k0=kbeg;k0<kend;k0+=BKt){
        LOAD_A_DIRECT(g_x, Nq);
        LOAD_B_DIRECT(A, Nq);   // rows p in 0..1023 = [Ar; Ai] contiguous
        __syncthreads();
        MMA_COMPUTE();
        __syncthreads();
    }
    MMA_EPILOG( g_part[blockIdx.z][(size_t)m*TMq + n] = v; )
}

// d = Ax + u - y (Ax summed from partials inline); z = y + s*d; u = (1-s)*d
__global__ void k_admm_zu(const float* __restrict__ y,
                          const float* __restrict__ log_eps,
                          const int* __restrict__ ns, int step){
    if(ns && step >= *ns) return;
    int b = blockIdx.x;
    float d0[4]; float s = 0.f;
    #pragma unroll
    for(int j=0;j<4;j++){
        int p = threadIdx.x + 256*j;
        size_t q = (size_t)b*TMq + p;
        float ax = 0.f;
        #pragma unroll
        for(int ks=0;ks<NSPLIT;ks++) ax += g_part[ks][q];
        float d = ax + g_u[q] - y[q];
        d0[j] = d; s += d*d;
    }
    __shared__ float red[256];
    red[threadIdx.x] = s; __syncthreads();
    for(int o=128;o>0;o>>=1){ if(threadIdx.x<o) red[threadIdx.x]+=red[threadIdx.x+o]; __syncthreads(); }
    float nrm = sqrtf(red[0]);
    float eps = load_eps(log_eps);
    float scale = fminf(1.0f, eps/fmaxf(nrm, 1e-12f));
    #pragma unroll
    for(int j=0;j<4;j++){
        int p = threadIdx.x + 256*j;
        size_t q = (size_t)b*TMq + p;
        g_z[q] = y[q] + scale*d0[j];
        g_u[q] = (1.0f - scale)*d0[j];
    }
}

__global__ void k_init_zu(const float* __restrict__ y, const float* __restrict__ u_in){
    int idx = blockIdx.x*256 + threadIdx.x;
    if(idx < Bq*TMq){ g_z[idx] = y[idx]; g_u[idx] = u_in[idx]; }
}

__global__ void k_writeout(float* __restrict__ out){
    int idx = blockIdx.x*256 + threadIdx.x;
    const int xtot = Bq*2*Nq;
    const int total = xtot + Bq*TMq;
    if(idx >= total) return;
    if(idx < xtot){
        int b = idx / (2*Nq); int rem = idx - b*2*Nq;
        out[idx] = (rem < Nq) ? g_x[(size_t)b*Nq + rem] : 0.0f;
    }else{
        out[idx] = g_u[idx - xtot];
    }
}

// ---------------- host ----------------
extern "C" void kernel_launch(void* const* d_in, const int* in_sizes, int n_in,
                              void* d_out, int out_size){
    const float* r_n     = (const float*)d_in[0];
    const float* y       = (const float*)d_in[1];
    const float* u_in    = (const float*)d_in[2];
    const float* A       = (const float*)d_in[3];
    const float* log_rho = (const float*)d_in[4];
    const float* log_eps = (const float*)d_in[5];
    const int*   ns      = (n_in > 6) ? (const int*)d_in[6] : nullptr;

    static float *pS=nullptr,*pX=nullptr,*pT1=nullptr,*pT2=nullptr,*pArn=nullptr;
    if(!pS){
        cudaGetSymbolAddress((void**)&pS,   g_S);
        cudaGetSymbolAddress((void**)&pX,   g_X);
        cudaGetSymbolAddress((void**)&pT1,  g_T1);
        cudaGetSymbolAddress((void**)&pT2,  g_T2);
        cudaGetSymbolAddress((void**)&pArn, g_Arn);
    }

    // S_block once (tensor cores, split-K over 2N)
    k_S_partial_mma<<<dim3(Mq/BN, TMq/BM, S_KSPLIT), 256>>>(A);
    k_S_combine<<<(Mq*Mq + 255)/256, 256>>>(log_rho);

    // lambda_max estimate
    k_pow_init<<<(TMq+255)/256, 256>>>();
    for(int i=0;i<8;i++){
        k_pow_mv<<<TMq, 256>>>();
        k_pow_norm<<<1, 1024>>>();
    }

    // Newton-Schulz inverse of S_block (6 iters, symmetrized)
    k_X_init<<<(TMq*TMq + 255)/256, 256>>>(log_rho);
    for(int i=0;i<6;i++){
        k_gemm_mma<<<dim3(TMq/BN, TMq/BM), 256>>>(pS, pX,  pT1);
        k_gemm_mma<<<dim3(TMq/BN, TMq/BM), 256>>>(pX, pT1, pT2);
        k_newton_upd<<<(TMq*TMq + 255)/256, 256>>>();
    }

    // Arn = A @ r_n (once)
    k_Amv_mma<<<dim3(TMq/BN, Bq/BM, NSPLIT), 256>>>(A, r_n);
    k_reduce<<<(Bq*TMq + 255)/256, 256>>>(pArn);

    // ADMM loop
    k_init_zu<<<(Bq*TMq + 255)/256, 256>>>(y, u_in);
    for(int step=0;step<5;step++){
        k_w_gemm_mma <<<dim3(TMq/BN, Bq/BM),          256>>>(ns, step);
        k_admm_x_mma <<<dim3(Nq/BN,  Bq/BM),          256>>>(A, r_n, ns, step);
        k_admm_Ax_mma<<<dim3(TMq/BN, Bq/BM, NSPLIT),  256>>>(A, ns, step);
        k_admm_zu    <<<Bq, 256>>>(y, log_eps, ns, step);
    }

    k_writeout<<<(Bq*2*Nq + Bq*TMq + 255)/256, 256>>>((float*)d_out);
}

// round 11
// speedup vs baseline: 2.1206x; 1.0804x over previous
#include <cuda_runtime.h>
#include <cstdint>

#define Bq  256
#define Mq  512
#define Nq  8192
#define TMq 1024
#define NSPLIT 8
#define GSPLIT 2
#define CSPLIT 4

#define BM 128
#define BN 64
#define BK 16
#define LDK 20
#define A_SZ (BM*LDK)           // 2560 floats
#define B_SZ (BN*LDK)           // 1280 floats
#define STG_F (2*A_SZ+2*B_SZ)   // 7680 floats per stage
#define STG_B (STG_F*4)         // 30720 bytes
#define SMEM_TOT (2*STG_B)      // 61440 bytes

// ---------------- device scratch ----------------
__device__ float g_Ah[2*Mq*Nq], g_Al[2*Mq*Nq];     // split of A (rows = [Ar;Ai], K-major)
__device__ float g_ATh[(size_t)Nq*TMq], g_ATl[(size_t)Nq*TMq];  // split of A^T (rows n, LD 1024)
__device__ float g_rnh[Bq*2*Nq], g_rnl[Bq*2*Nq];   // split of r_n (512 rows x 8192)
__device__ float g_Gpart[GSPLIT][TMq*TMq];
__device__ float g_S[TMq*TMq], g_Sh[TMq*TMq], g_Sl[TMq*TMq];
__device__ float g_X[TMq*TMq], g_Xh[TMq*TMq], g_Xl[TMq*TMq];
__device__ float g_T1th[TMq*TMq], g_T1tl[TMq*TMq]; // (S@X)^T split
__device__ float g_T2[TMq*TMq];
__device__ float g_C12p[CSPLIT][2*Bq*TMq];
__device__ float g_Arn[Bq*TMq];
__device__ float g_Vh[Bq*TMq], g_Vl[Bq*TMq];       // split of (z-u-Arn)
__device__ float g_Tmh[Bq*TMq], g_Tml[Bq*TMq];     // split of w
__device__ float g_x[Bq*Nq], g_xh[Bq*Nq], g_xl[Bq*Nq];
__device__ float g_z[Bq*TMq], g_u[Bq*TMq];
__device__ float g_part[NSPLIT][Bq*TMq];
__device__ float g_v[TMq], g_w[TMq], g_lam[1];

__device__ __forceinline__ float load_rho(const float* p){
    float v = *p; v = fminf(5.f, fmaxf(-5.f, v)); return expf(v);
}
__device__ __forceinline__ float load_eps(const float* p){
    float v = *p; v = fminf(0.f, fmaxf(-5.f, v)); return expf(v);
}
__device__ __forceinline__ uint32_t f2tf(float v){
    uint32_t r; asm("cvt.rna.tf32.f32 %0, %1;" : "=r"(r) : "f"(v)); return r;
}
__device__ __forceinline__ void split1(float v, float& h, float& l){
    h = __uint_as_float(f2tf(v));
    l = __uint_as_float(f2tf(v - h));
}
__device__ __forceinline__ void mma8(float* c, const uint32_t* a, const uint32_t* b){
    asm volatile("mma.sync.aligned.m16n8k8.row.col.f32.tf32.tf32.f32 "
        "{%0,%1,%2,%3}, {%4,%5,%6,%7}, {%8,%9}, {%0,%1,%2,%3};\n"
        : "+f"(c[0]),"+f"(c[1]),"+f"(c[2]),"+f"(c[3])
        : "r"(a[0]),"r"(a[1]),"r"(a[2]),"r"(a[3]), "r"(b[0]),"r"(b[1]));
}
__device__ __forceinline__ void cpa16(uint32_t saddr, const void* g){
    asm volatile("cp.async.ca.shared.global [%0], [%1], 16;" :: "r"(saddr), "l"(g));
}

// stage loader: pure cp.async of pre-split operands
__device__ __forceinline__ void load_stage(uint32_t sb,
        const float* __restrict__ Ah, const float* __restrict__ Al, size_t ldA, int m0,
        const float* __restrict__ Bh, const float* __restrict__ Bl, size_t ldB, int n0,
        int k0, int tid){
    #pragma unroll
    for(int i=0;i<2;i++){
        int idx = tid + i*256; int m_ = idx>>2; int kq = (idx&3)<<2;
        uint32_t off = (uint32_t)((m_*LDK + kq)*4);
        size_t gsrc = (size_t)(m0+m_)*ldA + k0 + kq;
        cpa16(sb + off,            Ah + gsrc);
        cpa16(sb + A_SZ*4 + off,   Al + gsrc);
    }
    {
        int m_ = tid>>2; int kq = (tid&3)<<2;
        uint32_t off = (uint32_t)((m_*LDK + kq)*4);
        size_t gsrc = (size_t)(n0+m_)*ldB + k0 + kq;
        cpa16(sb + 2*A_SZ*4 + off,          Bh + gsrc);
        cpa16(sb + (2*A_SZ+B_SZ)*4 + off,   Bl + gsrc);
    }
    asm volatile("cp.async.commit_group;");
}

// one BK=16 stage of 3xTF32 mma
__device__ __forceinline__ void mma_stage(const float* sAh, const float* sAl,
                                          const float* sBh, const float* sBl,
                                          float acc[2][4][4], int wm,int wn,int qr,int qc){
    #pragma unroll
    for(int k8=0;k8<BK;k8+=8){
        uint32_t ah[2][4], al[2][4], bh[4][2], bl[4][2];
        #pragma unroll
        for(int mt=0;mt<2;mt++){
            int m = wm*32 + mt*16;
            ah[mt][0]=__float_as_uint(sAh[(m+qr  )*LDK + k8+qc  ]); al[mt][0]=__float_as_uint(sAl[(m+qr  )*LDK + k8+qc  ]);
            ah[mt][1]=__float_as_uint(sAh[(m+qr+8)*LDK + k8+qc  ]); al[mt][1]=__float_as_uint(sAl[(m+qr+8)*LDK + k8+qc  ]);
            ah[mt][2]=__float_as_uint(sAh[(m+qr  )*LDK + k8+qc+4]); al[mt][2]=__float_as_uint(sAl[(m+qr  )*LDK + k8+qc+4]);
            ah[mt][3]=__float_as_uint(sAh[(m+qr+8)*LDK + k8+qc+4]); al[mt][3]=__float_as_uint(sAl[(m+qr+8)*LDK + k8+qc+4]);
        }
        #pragma unroll
        for(int nt=0;nt<4;nt++){
            int n = wn*32 + nt*8;
            bh[nt][0]=__float_as_uint(sBh[(n+qr)*LDK + k8+qc  ]); bl[nt][0]=__float_as_uint(sBl[(n+qr)*LDK + k8+qc  ]);
            bh[nt][1]=__float_as_uint(sBh[(n+qr)*LDK + k8+qc+4]); bl[nt][1]=__float_as_uint(sBl[(n+qr)*LDK + k8+qc+4]);
        }
        #pragma unroll
        for(int mt=0;mt<2;mt++)
            #pragma unroll
            for(int nt=0;nt<4;nt++){
                mma8(acc[mt][nt], ah[mt], bh[nt]);
                mma8(acc[mt][nt], ah[mt], bl[nt]);
                mma8(acc[mt][nt], al[mt], bh[nt]);
            }
    }
}

#define GEMM_PRE() \
    extern __shared__ float smem[]; \
    uint32_t sbase = (uint32_t)__cvta_generic_to_shared(smem); \
    float acc[2][4][4] = {}; \
    const int tid=threadIdx.x, lane=tid&31, wid=tid>>5; \
    const int wm=wid&3, wn=wid>>2, qr=lane>>2, qc=lane&3;

#define GEMM_LOOP(AH,AL,LDA,BH,BL,LDB,KBEG,KEND) do{ \
    const int nst = ((KEND)-(KBEG))/BK; \
    load_stage(sbase, AH,AL,(size_t)(LDA),m0, BH,BL,(size_t)(LDB),n0, (KBEG), tid); \
    for(int s=0;s<nst;s++){ \
        if(s+1<nst){ \
            load_stage(sbase + ((s+1)&1)*STG_B, AH,AL,(size_t)(LDA),m0, BH,BL,(size_t)(LDB),n0, (KBEG)+(s+1)*BK, tid); \
            asm volatile("cp.async.wait_group 1;"); \
        } else { asm volatile("cp.async.wait_group 0;"); } \
        __syncthreads(); \
        const float* st_ = smem + (s&1)*STG_F; \
        mma_stage(st_, st_+A_SZ, st_+2*A_SZ, st_+2*A_SZ+B_SZ, acc, wm, wn, qr, qc); \
        __syncthreads(); \
    } \
}while(0)

#define EPILOG(...) \
    _Pragma("unroll") for(int mt=0;mt<2;mt++) \
    _Pragma("unroll") for(int nt=0;nt<4;nt++) \
    _Pragma("unroll") for(int ci=0;ci<4;ci++){ \
        int m = m0 + wm*32 + mt*16 + qr + ((ci>>1)<<3); \
        int n = n0 + wn*32 + nt*8 + (qc<<1) + (ci&1); \
        float v = acc[mt][nt][ci]; __VA_ARGS__; }

// ---------------- split precompute kernels ----------------
__global__ void k_splitA(const float* __restrict__ A){
    int idx = blockIdx.x*256 + threadIdx.x;
    if(idx >= 2*Mq*Nq/4) return;
    float4 v = ((const float4*)A)[idx];
    float4 h, l;
    split1(v.x, h.x, l.x); split1(v.y, h.y, l.y);
    split1(v.z, h.z, l.z); split1(v.w, h.w, l.w);
    ((float4*)g_Ah)[idx] = h; ((float4*)g_Al)[idx] = l;
}
__global__ void k_split_rn(const float* __restrict__ rn){
    int idx = blockIdx.x*256 + threadIdx.x;
    if(idx >= Bq*2*Nq/4) return;
    float4 v = ((const float4*)rn)[idx];
    float4 h, l;
    split1(v.x, h.x, l.x); split1(v.y, h.y, l.y);
    split1(v.z, h.z, l.z); split1(v.w, h.w, l.w);
    ((float4*)g_rnh)[idx] = h; ((float4*)g_rnl)[idx] = l;
}
// transpose A (1024 x 8192) -> AT (8192 x 1024), split
__global__ void k_splitAT(const float* __restrict__ A){
    __shared__ float t[32][33];
    int x = blockIdx.x*32 + threadIdx.x;      // col n
    int y = blockIdx.y*32 + threadIdx.y;      // row p
    #pragma unroll
    for(int j=0;j<32;j+=8)
        t[threadIdx.y+j][threadIdx.x] = A[(size_t)(y+j)*Nq + x];
    __syncthreads();
    int xo = blockIdx.y*32 + threadIdx.x;     // p
    int yo = blockIdx.x*32 + threadIdx.y;     // n
    #pragma unroll
    for(int j=0;j<32;j+=8){
        float v = t[threadIdx.x][threadIdx.y+j];
        float h,l; split1(v,h,l);
        g_ATh[(size_t)(yo+j)*TMq + xo] = h;
        g_ATl[(size_t)(yo+j)*TMq + xo] = l;
    }
}

// ---------------- C12 = rn(512 rows) @ P^T, split-K ----------------
__global__ __launch_bounds__(256) void k_C12(){
    GEMM_PRE();
    const int n0 = blockIdx.x*BN, m0 = blockIdx.y*BM;
    const int kb = blockIdx.z*(Nq/CSPLIT);
    GEMM_LOOP(g_rnh,g_rnl,Nq, g_Ah,g_Al,Nq, kb, kb+Nq/CSPLIT);
    EPILOG( g_C12p[blockIdx.z][(size_t)m*TMq + n] = v )
}
__global__ void k_Arn_combine(){
    int idx = blockIdx.x*256 + threadIdx.x;
    if(idx >= Bq*Mq) return;
    int b = idx >> 9, m = idx & 511;
    float c1m=0,c1s=0,c2m=0,c2s=0;
    #pragma unroll
    for(int z=0;z<CSPLIT;z++){
        c1m += g_C12p[z][(size_t)(2*b  )*TMq + m];
        c1s += g_C12p[z][(size_t)(2*b  )*TMq + 512 + m];
        c2m += g_C12p[z][(size_t)(2*b+1)*TMq + m];
        c2s += g_C12p[z][(size_t)(2*b+1)*TMq + 512 + m];
    }
    g_Arn[(size_t)b*TMq + m]       = c1m - c2s;
    g_Arn[(size_t)b*TMq + 512 + m] = c2m + c1s;
}

// ---------------- G = P @ P^T (split-K 2) ----------------
__global__ __launch_bounds__(256) void k_G(){
    GEMM_PRE();
    const int n0 = blockIdx.x*BN, m0 = blockIdx.y*BM;
    const int kb = blockIdx.z*(Nq/GSPLIT);
    GEMM_LOOP(g_Ah,g_Al,Nq, g_Ah,g_Al,Nq, kb, kb+Nq/GSPLIT);
    EPILOG( g_Gpart[blockIdx.z][(size_t)m*TMq + n] = v )
}
__global__ void k_S_from_G(const float* __restrict__ log_rho){
    int idx = blockIdx.x*256 + threadIdx.x;
    if(idx >= Mq*Mq) return;
    int i = idx/Mq, j = idx%Mq;
    float g00=0,g01=0,g10=0,g11=0;
    #pragma unroll
    for(int z=0;z<GSPLIT;z++){
        g00 += g_Gpart[z][(size_t)i*TMq + j];
        g01 += g_Gpart[z][(size_t)i*TMq + 512 + j];
        g10 += g_Gpart[z][(size_t)(512+i)*TMq + j];
        g11 += g_Gpart[z][(size_t)(512+i)*TMq + 512 + j];
    }
    float rho = load_rho(log_rho);
    float sr = g00 + g11 + ((i==j) ? 1.0f/(rho+1e-12f) : 0.0f);
    float si = g10 - g01;
    size_t i00 = (size_t)i*TMq + j,        i01 = (size_t)i*TMq + 512 + j;
    size_t i10 = (size_t)(512+i)*TMq + j,  i11 = (size_t)(512+i)*TMq + 512 + j;
    float h,l;
    g_S[i00]=sr;  split1(sr,h,l);  g_Sh[i00]=h; g_Sl[i00]=l;
                                   g_Sh[i11]=h; g_Sl[i11]=l;  g_S[i11]=sr;
    g_S[i01]=-si; split1(-si,h,l); g_Sh[i01]=h; g_Sl[i01]=l;
    g_S[i10]=si;  split1(si,h,l);  g_Sh[i10]=h; g_Sl[i10]=l;
}

// ---------------- power iteration ----------------
__global__ void k_pow_init(){
    int i = blockIdx.x*256 + threadIdx.x;
    if(i < TMq) g_v[i] = 1.0f + 0.001f*(float)i;
}
__global__ void k_pow_mv(){
    int row = blockIdx.x;
    float s = 0.f;
    for(int j=threadIdx.x;j<TMq;j+=256) s += g_S[(size_t)row*TMq + j]*g_v[j];
    __shared__ float red[256];
    red[threadIdx.x] = s; __syncthreads();
    for(int o=128;o>0;o>>=1){ if(threadIdx.x<o) red[threadIdx.x]+=red[threadIdx.x+o]; __syncthreads(); }
    if(threadIdx.x==0) g_w[row] = red[0];
}
__global__ void k_pow_norm(){
    __shared__ float red[1024];
    int tid = threadIdx.x;
    float w = g_w[tid];
    red[tid] = w*w; __syncthreads();
    for(int o=512;o>0;o>>=1){ if(tid<o) red[tid]+=red[tid+o]; __syncthreads(); }
    float nn = sqrtf(red[0]);
    g_v[tid] = g_w[tid]/nn;
    if(tid==0) g_lam[0] = nn;
}
__global__ void k_X_init(const float* __restrict__ log_rho){
    int idx = blockIdx.x*256 + threadIdx.x;
    if(idx >= TMq*TMq) return;
    int i = idx/TMq, j = idx%TMq;
    float rho = load_rho(log_rho);
    float c = (i==j) ? 2.0f/(1.1f*g_lam[0] + 1.0f/(rho + 1e-12f)) : 0.0f;
    float h,l; split1(c,h,l);
    g_X[idx] = c; g_Xh[idx] = h; g_Xl[idx] = l;
}

// ---------------- Newton GEMMs ----------------
// T1t = (S @ X)^T  (X symmetric -> B-side reads X rows)
__global__ __launch_bounds__(256) void k_T1(){
    GEMM_PRE();
    const int n0 = blockIdx.x*BN, m0 = blockIdx.y*BM;
    GEMM_LOOP(g_Sh,g_Sl,TMq, g_Xh,g_Xl,TMq, 0, TMq);
    EPILOG( float h; float l; split1(v,h,l);
            g_T1th[(size_t)n*TMq + m]=h; g_T1tl[(size_t)n*TMq + m]=l )
}
// T2 = X @ T1 = X @ (T1t)^T
__global__ __launch_bounds__(256) void k_T2(){
    GEMM_PRE();
    const int n0 = blockIdx.x*BN, m0 = blockIdx.y*BM;
    GEMM_LOOP(g_Xh,g_Xl,TMq, g_T1th,g_T1tl,TMq, 0, TMq);
    EPILOG( g_T2[(size_t)m*TMq + n] = v )
}
__global__ void k_newton_upd(){
    int idx = blockIdx.x*256 + threadIdx.x;
    if(idx >= TMq*TMq) return;
    int i = idx/TMq, j = idx%TMq;
    float v = 2.0f*g_X[idx] - 0.5f*(g_T2[idx] + g_T2[(size_t)j*TMq + i]);
    float h,l; split1(v,h,l);
    g_X[idx] = v; g_Xh[idx] = h; g_Xl[idx] = l;
}

// ---------------- ADMM loop ----------------
__global__ void k_init_V(const float* __restrict__ y, const float* __restrict__ u_in){
    int idx = blockIdx.x*256 + threadIdx.x;
    if(idx >= Bq*TMq) return;
    float zz = y[idx], uu = u_in[idx];
    g_z[idx] = zz; g_u[idx] = uu;
    float vv = zz - uu - g_Arn[idx];
    float h,l; split1(vv,h,l);
    g_Vh[idx] = h; g_Vl[idx] = l;
}
// w = V @ X  -> Tm split
__global__ __launch_bounds__(256) void k_w(const int* __restrict__ ns, int step){
    if(ns && step >= *ns) return;
    GEMM_PRE();
    const int n0 = blockIdx.x*BN, m0 = blockIdx.y*BM;
    GEMM_LOOP(g_Vh,g_Vl,TMq, g_Xh,g_Xl,TMq, 0, TMq);
    EPILOG( float h; float l; split1(v,h,l);
            g_Tmh[(size_t)m*TMq + n]=h; g_Tml[(size_t)m*TMq + n]=l )
}
// x = relu(rn_r + w @ A)  (B-side = AT rows)
__global__ __launch_bounds__(256) void k_x(const float* __restrict__ r_n,
                                           const int* __restrict__ ns, int step){
    if(ns && step >= *ns) return;
    GEMM_PRE();
    const int n0 = blockIdx.x*BN, m0 = blockIdx.y*BM;
    GEMM_LOOP(g_Tmh,g_Tml,TMq, g_ATh,g_ATl,TMq, 0, TMq);
    EPILOG( float xv = fmaxf(0.0f, r_n[(size_t)m*2*Nq + n] + v);
            g_x[(size_t)m*Nq + n] = xv;
            float h; float l; split1(xv,h,l);
            g_xh[(size_t)m*Nq + n]=h; g_xl[(size_t)m*Nq + n]=l )
}
// Ax partials = x @ P^T, split-K 8
__global__ __launch_bounds__(256) void k_Ax(const int* __restrict__ ns, int step){
    if(ns && step >= *ns) return;
    GEMM_PRE();
    const int n0 = blockIdx.x*BN, m0 = blockIdx.y*BM;
    const int kb = blockIdx.z*(Nq/NSPLIT);
    GEMM_LOOP(g_xh,g_xl,Nq, g_Ah,g_Al,Nq, kb, kb+Nq/NSPLIT);
    EPILOG( g_part[blockIdx.z][(size_t)m*TMq + n] = v )
}
// d = Ax + u - y; z,u update; V = z-u-Arn split
__global__ void k_zu(const float* __restrict__ y,
                     const float* __restrict__ log_eps,
                     const int* __restrict__ ns, int step){
    if(ns && step >= *ns) return;
    int b = blockIdx.x;
    float d0[4]; float s = 0.f;
    #pragma unroll
    for(int j=0;j<4;j++){
        int p = threadIdx.x + 256*j;
        size_t q = (size_t)b*TMq + p;
        float ax = 0.f;
        #pragma unroll
        for(int ks=0;ks<NSPLIT;ks++) ax += g_part[ks][q];
        float d = ax + g_u[q] - y[q];
        d0[j] = d; s += d*d;
    }
    __shared__ float red[256];
    red[threadIdx.x] = s; __syncthreads();
    for(int o=128;o>0;o>>=1){ if(threadIdx.x<o) red[threadIdx.x]+=red[threadIdx.x+o]; __syncthreads(); }
    float nrm = sqrtf(red[0]);
    float eps = load_eps(log_eps);
    float scale = fminf(1.0f, eps/fmaxf(nrm, 1e-12f));
    #pragma unroll
    for(int j=0;j<4;j++){
        int p = threadIdx.x + 256*j;
        size_t q = (size_t)b*TMq + p;
        float zz = y[q] + scale*d0[j];
        float uu = (1.0f - scale)*d0[j];
        g_z[q] = zz; g_u[q] = uu;
        float vv = zz - uu - g_Arn[q];
        float h,l; split1(vv,h,l);
        g_Vh[q] = h; g_Vl[q] = l;
    }
}

__global__ void k_writeout(float* __restrict__ out){
    int idx = blockIdx.x*256 + threadIdx.x;
    const int xtot = Bq*2*Nq;
    const int total = xtot + Bq*TMq;
    if(idx >= total) return;
    if(idx < xtot){
        int b = idx / (2*Nq); int rem = idx - b*2*Nq;
        out[idx] = (rem < Nq) ? g_x[(size_t)b*Nq + rem] : 0.0f;
    }else{
        out[idx] = g_u[idx - xtot];
    }
}

// ---------------- host ----------------
extern "C" void kernel_launch(void* const* d_in, const int* in_sizes, int n_in,
                              void* d_out, int out_size){
    const float* r_n     = (const float*)d_in[0];
    const float* y       = (const float*)d_in[1];
    const float* u_in    = (const float*)d_in[2];
    const float* A       = (const float*)d_in[3];
    const float* log_rho = (const float*)d_in[4];
    const float* log_eps = (const float*)d_in[5];
    const int*   ns      = (n_in > 6) ? (const int*)d_in[6] : nullptr;

    static bool attr_done = false;
    if(!attr_done){
        cudaFuncSetAttribute(k_C12, cudaFuncAttributeMaxDynamicSharedMemorySize, SMEM_TOT);
        cudaFuncSetAttribute(k_G,   cudaFuncAttributeMaxDynamicSharedMemorySize, SMEM_TOT);
        cudaFuncSetAttribute(k_T1,  cudaFuncAttributeMaxDynamicSharedMemorySize, SMEM_TOT);
        cudaFuncSetAttribute(k_T2,  cudaFuncAttributeMaxDynamicSharedMemorySize, SMEM_TOT);
        cudaFuncSetAttribute(k_w,   cudaFuncAttributeMaxDynamicSharedMemorySize, SMEM_TOT);
        cudaFuncSetAttribute(k_x,   cudaFuncAttributeMaxDynamicSharedMemorySize, SMEM_TOT);
        cudaFuncSetAttribute(k_Ax,  cudaFuncAttributeMaxDynamicSharedMemorySize, SMEM_TOT);
        attr_done = true;
    }

    // 1-3: operand splits
    k_splitA  <<<(2*Mq*Nq/4 + 255)/256, 256>>>(A);
    k_splitAT <<<dim3(Nq/32, TMq/32), dim3(32,8)>>>(A);
    k_split_rn<<<(Bq*2*Nq/4 + 255)/256, 256>>>(r_n);

    // 4-5: Arn = A @ r_n
    k_C12<<<dim3(TMq/BN, 512/BM, CSPLIT), 256, SMEM_TOT>>>();
    k_Arn_combine<<<(Bq*Mq + 255)/256, 256>>>();

    // 6: G = P P^T  (captured by ncu)
    k_G<<<dim3(TMq/BN, TMq/BM, GSPLIT), 256, SMEM_TOT>>>();
    k_S_from_G<<<(Mq*Mq + 255)/256, 256>>>(log_rho);

    // power iteration
    k_pow_init<<<(TMq+255)/256, 256>>>();
    for(int i=0;i<8;i++){
        k_pow_mv<<<TMq, 256>>>();
        k_pow_norm<<<1, 1024>>>();
    }

    // Newton-Schulz (6 iters, symmetrized)
    k_X_init<<<(TMq*TMq + 255)/256, 256>>>(log_rho);
    for(int i=0;i<6;i++){
        k_T1<<<dim3(TMq/BN, TMq/BM), 256, SMEM_TOT>>>();
        k_T2<<<dim3(TMq/BN, TMq/BM), 256, SMEM_TOT>>>();
        k_newton_upd<<<(TMq*TMq + 255)/256, 256>>>();
    }

    // ADMM loop
    k_init_V<<<(Bq*TMq + 255)/256, 256>>>(y, u_in);
    for(int step=0;step<5;step++){
        k_w <<<dim3(TMq/BN, Bq/BM),          256, SMEM_TOT>>>(ns, step);
        k_x <<<dim3(Nq/BN,  Bq/BM),          256, SMEM_TOT>>>(r_n, ns, step);
        k_Ax<<<dim3(TMq/BN, Bq/BM, NSPLIT),  256, SMEM_TOT>>>(ns, step);
        k_zu<<<Bq, 256>>>(y, log_eps, ns, step);
    }

    k_writeout<<<(Bq*2*Nq + Bq*TMq + 255)/256, 256>>>((float*)d_out);
}

// round 16
// speedup vs baseline: 2.2721x; 1.0715x over previous
#include <cuda_runtime.h>
#include <cstdint>

#define Bq  256
#define Mq  512
#define Nq  8192
#define TMq 1024
#define NSPLIT 8
#define GSPLIT 2
#define CSPLIT 4

#define BM 128
#define BN 64
#define BK 16
#define LDK2 20                 // float2 per row: 16 data + 4 pad (160B row)
#define A_F2 (BM*LDK2)          // 2560 float2
#define B_F2 (BN*LDK2)          // 1280 float2
#define STG_F2 (A_F2+B_F2)      // 3840 float2 per stage
#define STG_B (STG_F2*8)        // 30720 bytes
#define SMEM_TOT (2*STG_B)      // 61440 bytes

// ---------------- device scratch (hi/lo interleaved as float2) ----------------
__device__ float2 g_A2 [(size_t)2*Mq*Nq];      // P = [Ar;Ai], K-major, (h,l)
__device__ float2 g_AT2[(size_t)Nq*TMq];       // A^T rows n, LD 1024
__device__ float2 g_rn2[(size_t)2*Bq*Nq];      // r_n as 512 rows x 8192
__device__ float2 g_S2 [TMq*TMq];
__device__ float2 g_X2 [TMq*TMq];
__device__ float2 g_T1t2[TMq*TMq];             // (S@X)^T
__device__ float2 g_V2 [Bq*TMq];               // z-u-Arn
__device__ float2 g_Tm2[Bq*TMq];               // w
__device__ float2 g_x2 [Bq*Nq];
// plain fp32
__device__ float g_Gpart[GSPLIT][TMq*TMq];
__device__ float g_S[TMq*TMq], g_X[TMq*TMq], g_T2[TMq*TMq];
__device__ float g_C12p[CSPLIT][2*Bq*TMq];
__device__ float g_Arn[Bq*TMq];
__device__ float g_x[Bq*Nq];
__device__ float g_z[Bq*TMq], g_u[Bq*TMq];
__device__ float g_part[NSPLIT][Bq*TMq];
__device__ float g_v[TMq], g_w[TMq], g_lam[1];

__device__ __forceinline__ float load_rho(const float* p){
    float v = *p; v = fminf(5.f, fmaxf(-5.f, v)); return expf(v);
}
__device__ __forceinline__ float load_eps(const float* p){
    float v = *p; v = fminf(0.f, fmaxf(-5.f, v)); return expf(v);
}
__device__ __forceinline__ uint32_t f2tf(float v){
    uint32_t r; asm("cvt.rna.tf32.f32 %0, %1;" : "=r"(r) : "f"(v)); return r;
}
__device__ __forceinline__ float2 split2(float v){
    float h = __uint_as_float(f2tf(v));
    float l = __uint_as_float(f2tf(v - h));
    return make_float2(h, l);
}
__device__ __forceinline__ void mma8(float* c, const uint32_t* a, const uint32_t* b){
    asm volatile("mma.sync.aligned.m16n8k8.row.col.f32.tf32.tf32.f32 "
        "{%0,%1,%2,%3}, {%4,%5,%6,%7}, {%8,%9}, {%0,%1,%2,%3};\n"
        : "+f"(c[0]),"+f"(c[1]),"+f"(c[2]),"+f"(c[3])
        : "r"(a[0]),"r"(a[1]),"r"(a[2]),"r"(a[3]), "r"(b[0]),"r"(b[1]));
}
__device__ __forceinline__ void cpa16(uint32_t saddr, const void* g){
    asm volatile("cp.async.ca.shared.global [%0], [%1], 16;" :: "r"(saddr), "l"(g));
}

// stage loader: pure cp.async of (h,l)-interleaved operands. k0 in K-element units.
__device__ __forceinline__ void load_stage(uint32_t sb,
        const float2* __restrict__ A2, size_t ldA, int m0,
        const float2* __restrict__ B2, size_t ldB, int n0,
        int k0, int tid){
    #pragma unroll
    for(int i=0;i<4;i++){                 // A: 128 rows x 8 chunks = 1024
        int idx = tid + i*256; int m_ = idx>>3; int c = idx&7;
        cpa16(sb + (uint32_t)((m_*LDK2 + c*2)*8),
              A2 + (size_t)(m0+m_)*ldA + k0 + c*2);
    }
    #pragma unroll
    for(int i=0;i<2;i++){                 // B: 64 rows x 8 chunks = 512
        int idx = tid + i*256; int m_ = idx>>3; int c = idx&7;
        cpa16(sb + (uint32_t)(A_F2*8 + (m_*LDK2 + c*2)*8),
              B2 + (size_t)(n0+m_)*ldB + k0 + c*2);
    }
    asm volatile("cp.async.commit_group;");
}

// one BK=16 stage of 3xTF32 mma; fragments via 64-bit LDS ((h,l) pairs)
__device__ __forceinline__ void mma_stage(const float2* sA, const float2* sB,
                                          float acc[2][4][4], int wm,int wn,int qr,int qc){
    #pragma unroll
    for(int k8=0;k8<BK;k8+=8){
        uint32_t ah[2][4], al[2][4], bh[4][2], bl[4][2];
        #pragma unroll
        for(int mt=0;mt<2;mt++){
            int m = wm*32 + mt*16;
            float2 p0 = sA[(m+qr  )*LDK2 + k8+qc  ];
            float2 p1 = sA[(m+qr+8)*LDK2 + k8+qc  ];
            float2 p2 = sA[(m+qr  )*LDK2 + k8+qc+4];
            float2 p3 = sA[(m+qr+8)*LDK2 + k8+qc+4];
            ah[mt][0]=__float_as_uint(p0.x); al[mt][0]=__float_as_uint(p0.y);
            ah[mt][1]=__float_as_uint(p1.x); al[mt][1]=__float_as_uint(p1.y);
            ah[mt][2]=__float_as_uint(p2.x); al[mt][2]=__float_as_uint(p2.y);
            ah[mt][3]=__float_as_uint(p3.x); al[mt][3]=__float_as_uint(p3.y);
        }
        #pragma unroll
        for(int nt=0;nt<4;nt++){
            int n = wn*32 + nt*8;
            float2 q0 = sB[(n+qr)*LDK2 + k8+qc  ];
            float2 q1 = sB[(n+qr)*LDK2 + k8+qc+4];
            bh[nt][0]=__float_as_uint(q0.x); bl[nt][0]=__float_as_uint(q0.y);
            bh[nt][1]=__float_as_uint(q1.x); bl[nt][1]=__float_as_uint(q1.y);
        }
        #pragma unroll
        for(int mt=0;mt<2;mt++)
            #pragma unroll
            for(int nt=0;nt<4;nt++){
                mma8(acc[mt][nt], ah[mt], bh[nt]);
                mma8(acc[mt][nt], ah[mt], bl[nt]);
                mma8(acc[mt][nt], al[mt], bh[nt]);
            }
    }
}

#define GEMM_PRE() \
    extern __shared__ float2 smem[]; \
    uint32_t sbase = (uint32_t)__cvta_generic_to_shared(smem); \
    float acc[2][4][4] = {}; \
    const int tid=threadIdx.x, lane=tid&31, wid=tid>>5; \
    const int wm=wid&3, wn=wid>>2, qr=lane>>2, qc=lane&3;

#define GEMM_LOOP(A2P,LDA,B2P,LDB,KBEG,KEND) do{ \
    const int nst = ((KEND)-(KBEG))/BK; \
    load_stage(sbase, A2P,(size_t)(LDA),m0, B2P,(size_t)(LDB),n0, (KBEG), tid); \
    for(int s=0;s<nst;s++){ \
        if(s+1<nst){ \
            load_stage(sbase + ((s+1)&1)*STG_B, A2P,(size_t)(LDA),m0, B2P,(size_t)(LDB),n0, (KBEG)+(s+1)*BK, tid); \
            asm volatile("cp.async.wait_group 1;"); \
        } else { asm volatile("cp.async.wait_group 0;"); } \
        __syncthreads(); \
        const float2* st_ = smem + (s&1)*STG_F2; \
        mma_stage(st_, st_+A_F2, acc, wm, wn, qr, qc); \
        __syncthreads(); \
    } \
}while(0)

#define EPILOG(...) \
    _Pragma("unroll") for(int mt=0;mt<2;mt++) \
    _Pragma("unroll") for(int nt=0;nt<4;nt++) \
    _Pragma("unroll") for(int ci=0;ci<4;ci++){ \
        int m = m0 + wm*32 + mt*16 + qr + ((ci>>1)<<3); \
        int n = n0 + wn*32 + nt*8 + (qc<<1) + (ci&1); \
        float v = acc[mt][nt][ci]; __VA_ARGS__; }

// ---------------- split precompute kernels ----------------
__global__ void k_splitA(const float* __restrict__ A){
    int idx = blockIdx.x*256 + threadIdx.x;
    if(idx >= 2*Mq*Nq/4) return;
    float4 v = ((const float4*)A)[idx];
    float2 a = split2(v.x), b = split2(v.y), c = split2(v.z), d = split2(v.w);
    float4* dst = (float4*)g_A2;
    dst[2*idx  ] = make_float4(a.x,a.y,b.x,b.y);
    dst[2*idx+1] = make_float4(c.x,c.y,d.x,d.y);
}
__global__ void k_split_rn(const float* __restrict__ rn){
    int idx = blockIdx.x*256 + threadIdx.x;
    if(idx >= Bq*2*Nq/4) return;
    float4 v = ((const float4*)rn)[idx];
    float2 a = split2(v.x), b = split2(v.y), c = split2(v.z), d = split2(v.w);
    float4* dst = (float4*)g_rn2;
    dst[2*idx  ] = make_float4(a.x,a.y,b.x,b.y);
    dst[2*idx+1] = make_float4(c.x,c.y,d.x,d.y);
}
// transpose A (1024 x 8192) -> AT (8192 x 1024), split
__global__ void k_splitAT(const float* __restrict__ A){
    __shared__ float t[32][33];
    int x = blockIdx.x*32 + threadIdx.x;      // col n
    int y = blockIdx.y*32 + threadIdx.y;      // row p
    #pragma unroll
    for(int j=0;j<32;j+=8)
        t[threadIdx.y+j][threadIdx.x] = A[(size_t)(y+j)*Nq + x];
    __syncthreads();
    int xo = blockIdx.y*32 + threadIdx.x;     // p
    int yo = blockIdx.x*32 + threadIdx.y;     // n
    #pragma unroll
    for(int j=0;j<32;j+=8)
        g_AT2[(size_t)(yo+j)*TMq + xo] = split2(t[threadIdx.x][threadIdx.y+j]);
}

// ---------------- C12 = rn(512 rows) @ P^T, split-K ----------------
__global__ __launch_bounds__(256) void k_C12(){
    GEMM_PRE();
    const int n0 = blockIdx.x*BN, m0 = blockIdx.y*BM;
    const int kb = blockIdx.z*(Nq/CSPLIT);
    GEMM_LOOP(g_rn2,Nq, g_A2,Nq, kb, kb+Nq/CSPLIT);
    EPILOG( g_C12p[blockIdx.z][(size_t)m*TMq + n] = v )
}
__global__ void k_Arn_combine(){
    int idx = blockIdx.x*256 + threadIdx.x;
    if(idx >= Bq*Mq) return;
    int b = idx >> 9, m = idx & 511;
    float c1m=0,c1s=0,c2m=0,c2s=0;
    #pragma unroll
    for(int z=0;z<CSPLIT;z++){
        c1m += g_C12p[z][(size_t)(2*b  )*TMq + m];
        c1s += g_C12p[z][(size_t)(2*b  )*TMq + 512 + m];
        c2m += g_C12p[z][(size_t)(2*b+1)*TMq + m];
        c2s += g_C12p[z][(size_t)(2*b+1)*TMq + 512 + m];
    }
    g_Arn[(size_t)b*TMq + m]       = c1m - c2s;
    g_Arn[(size_t)b*TMq + 512 + m] = c2m + c1s;
}

// ---------------- G = P @ P^T (split-K 2) ----------------
__global__ __launch_bounds__(256) void k_G(){
    GEMM_PRE();
    const int n0 = blockIdx.x*BN, m0 = blockIdx.y*BM;
    const int kb = blockIdx.z*(Nq/GSPLIT);
    GEMM_LOOP(g_A2,Nq, g_A2,Nq, kb, kb+Nq/GSPLIT);
    EPILOG( g_Gpart[blockIdx.z][(size_t)m*TMq + n] = v )
}
__global__ void k_S_from_G(const float* __restrict__ log_rho){
    int idx = blockIdx.x*256 + threadIdx.x;
    if(idx >= Mq*Mq) return;
    int i = idx/Mq, j = idx%Mq;
    float g00=0,g01=0,g10=0,g11=0;
    #pragma unroll
    for(int z=0;z<GSPLIT;z++){
        g00 += g_Gpart[z][(size_t)i*TMq + j];
        g01 += g_Gpart[z][(size_t)i*TMq + 512 + j];
        g10 += g_Gpart[z][(size_t)(512+i)*TMq + j];
        g11 += g_Gpart[z][(size_t)(512+i)*TMq + 512 + j];
    }
    float rho = load_rho(log_rho);
    float sr = g00 + g11 + ((i==j) ? 1.0f/(rho+1e-12f) : 0.0f);
    float si = g10 - g01;
    size_t i00 = (size_t)i*TMq + j,        i01 = (size_t)i*TMq + 512 + j;
    size_t i10 = (size_t)(512+i)*TMq + j,  i11 = (size_t)(512+i)*TMq + 512 + j;
    float2 sp = split2(sr), sn = split2(-si), spp = split2(si);
    g_S[i00]=sr;  g_S2[i00]=sp;
    g_S[i11]=sr;  g_S2[i11]=sp;
    g_S[i01]=-si; g_S2[i01]=sn;
    g_S[i10]=si;  g_S2[i10]=spp;
}

// ---------------- power iteration ----------------
__global__ void k_pow_init(){
    int i = blockIdx.x*256 + threadIdx.x;
    if(i < TMq) g_v[i] = 1.0f + 0.001f*(float)i;
}
__global__ void k_pow_mv(){
    int row = blockIdx.x;
    float s = 0.f;
    for(int j=threadIdx.x;j<TMq;j+=256) s += g_S[(size_t)row*TMq + j]*g_v[j];
    __shared__ float red[256];
    red[threadIdx.x] = s; __syncthreads();
    for(int o=128;o>0;o>>=1){ if(threadIdx.x<o) red[threadIdx.x]+=red[threadIdx.x+o]; __syncthreads(); }
    if(threadIdx.x==0) g_w[row] = red[0];
}
__global__ void k_pow_norm(){
    __shared__ float red[1024];
    int tid = threadIdx.x;
    float w = g_w[tid];
    red[tid] = w*w; __syncthreads();
    for(int o=512;o>0;o>>=1){ if(tid<o) red[tid]+=red[tid+o]; __syncthreads(); }
    float nn = sqrtf(red[0]);
    g_v[tid] = g_w[tid]/nn;
    if(tid==0) g_lam[0] = nn;
}
__global__ void k_X_init(const float* __restrict__ log_rho){
    int idx = blockIdx.x*256 + threadIdx.x;
    if(idx >= TMq*TMq) return;
    int i = idx/TMq, j = idx%TMq;
    float rho = load_rho(log_rho);
    float c = (i==j) ? 2.0f/(1.1f*g_lam[0] + 1.0f/(rho + 1e-12f)) : 0.0f;
    g_X[idx] = c; g_X2[idx] = split2(c);
}

// ---------------- Newton GEMMs ----------------
// T1t = (S @ X)^T  (X symmetric -> B-side reads X rows)
__global__ __launch_bounds__(256) void k_T1(){
    GEMM_PRE();
    const int n0 = blockIdx.x*BN, m0 = blockIdx.y*BM;
    GEMM_LOOP(g_S2,TMq, g_X2,TMq, 0, TMq);
    EPILOG( g_T1t2[(size_t)n*TMq + m] = split2(v) )
}
// T2 = X @ T1 = X @ (T1t)^T
__global__ __launch_bounds__(256) void k_T2(){
    GEMM_PRE();
    const int n0 = blockIdx.x*BN, m0 = blockIdx.y*BM;
    GEMM_LOOP(g_X2,TMq, g_T1t2,TMq, 0, TMq);
    EPILOG( g_T2[(size_t)m*TMq + n] = v )
}
__global__ void k_newton_upd(){
    int idx = blockIdx.x*256 + threadIdx.x;
    if(idx >= TMq*TMq) return;
    int i = idx/TMq, j = idx%TMq;
    float v = 2.0f*g_X[idx] - 0.5f*(g_T2[idx] + g_T2[(size_t)j*TMq + i]);
    g_X[idx] = v; g_X2[idx] = split2(v);
}

// ---------------- ADMM loop ----------------
__global__ void k_init_V(const float* __restrict__ y, const float* __restrict__ u_in){
    int idx = blockIdx.x*256 + threadIdx.x;
    if(idx >= Bq*TMq) return;
    float zz = y[idx], uu = u_in[idx];
    g_z[idx] = zz; g_u[idx] = uu;
    g_V2[idx] = split2(zz - uu - g_Arn[idx]);
}
// w = V @ X  -> Tm split
__global__ __launch_bounds__(256) void k_w(const int* __restrict__ ns, int step){
    if(ns && step >= *ns) return;
    GEMM_PRE();
    const int n0 = blockIdx.x*BN, m0 = blockIdx.y*BM;
    GEMM_LOOP(g_V2,TMq, g_X2,TMq, 0, TMq);
    EPILOG( g_Tm2[(size_t)m*TMq + n] = split2(v) )
}
// x = relu(rn_r + w @ A)  (B-side = AT rows)
__global__ __launch_bounds__(256) void k_x(const float* __restrict__ r_n,
                                           const int* __restrict__ ns, int step){
    if(ns && step >= *ns) return;
    GEMM_PRE();
    const int n0 = blockIdx.x*BN, m0 = blockIdx.y*BM;
    GEMM_LOOP(g_Tm2,TMq, g_AT2,TMq, 0, TMq);
    EPILOG( float xv = fmaxf(0.0f, r_n[(size_t)m*2*Nq + n] + v);
            g_x[(size_t)m*Nq + n] = xv;
            g_x2[(size_t)m*Nq + n] = split2(xv) )
}
// Ax partials = x @ P^T, split-K 8
__global__ __launch_bounds__(256) void k_Ax(const int* __restrict__ ns, int step){
    if(ns && step >= *ns) return;
    GEMM_PRE();
    const int n0 = blockIdx.x*BN, m0 = blockIdx.y*BM;
    const int kb = blockIdx.z*(Nq/NSPLIT);
    GEMM_LOOP(g_x2,Nq, g_A2,Nq, kb, kb+Nq/NSPLIT);
    EPILOG( g_part[blockIdx.z][(size_t)m*TMq + n] = v )
}
// d = Ax + u - y; z,u update; V = z-u-Arn split
__global__ void k_zu(const float* __restrict__ y,
                     const float* __restrict__ log_eps,
                     const int* __restrict__ ns, int step){
    if(ns && step >= *ns) return;
    int b = blockIdx.x;
    float d0[4]; float s = 0.f;
    #pragma unroll
    for(int j=0;j<4;j++){
        int p = threadIdx.x + 256*j;
        size_t q = (size_t)b*TMq + p;
        float ax = 0.f;
        #pragma unroll
        for(int ks=0;ks<NSPLIT;ks++) ax += g_part[ks][q];
        float d = ax + g_u[q] - y[q];
        d0[j] = d; s += d*d;
    }
    __shared__ float red[256];
    red[threadIdx.x] = s; __syncthreads();
    for(int o=128;o>0;o>>=1){ if(threadIdx.x<o) red[threadIdx.x]+=red[threadIdx.x+o]; __syncthreads(); }
    float nrm = sqrtf(red[0]);
    float eps = load_eps(log_eps);
    float scale = fminf(1.0f, eps/fmaxf(nrm, 1e-12f));
    #pragma unroll
    for(int j=0;j<4;j++){
        int p = threadIdx.x + 256*j;
        size_t q = (size_t)b*TMq + p;
        float zz = y[q] + scale*d0[j];
        float uu = (1.0f - scale)*d0[j];
        g_z[q] = zz; g_u[q] = uu;
        g_V2[q] = split2(zz - uu - g_Arn[q]);
    }
}

__global__ void k_writeout(float* __restrict__ out){
    int idx = blockIdx.x*256 + threadIdx.x;
    const int xtot = Bq*2*Nq;
    const int total = xtot + Bq*TMq;
    if(idx >= total) return;
    if(idx < xtot){
        int b = idx / (2*Nq); int rem = idx - b*2*Nq;
        out[idx] = (rem < Nq) ? g_x[(size_t)b*Nq + rem] : 0.0f;
    }else{
        out[idx] = g_u[idx - xtot];
    }
}

// ---------------- host ----------------
extern "C" void kernel_launch(void* const* d_in, const int* in_sizes, int n_in,
                              void* d_out, int out_size){
    const float* r_n     = (const float*)d_in[0];
    const float* y       = (const float*)d_in[1];
    const float* u_in    = (const float*)d_in[2];
    const float* A       = (const float*)d_in[3];
    const float* log_rho = (const float*)d_in[4];
    const float* log_eps = (const float*)d_in[5];
    const int*   ns      = (n_in > 6) ? (const int*)d_in[6] : nullptr;

    static bool attr_done = false;
    if(!attr_done){
        cudaFuncSetAttribute(k_C12, cudaFuncAttributeMaxDynamicSharedMemorySize, SMEM_TOT);
        cudaFuncSetAttribute(k_G,   cudaFuncAttributeMaxDynamicSharedMemorySize, SMEM_TOT);
        cudaFuncSetAttribute(k_T1,  cudaFuncAttributeMaxDynamicSharedMemorySize, SMEM_TOT);
        cudaFuncSetAttribute(k_T2,  cudaFuncAttributeMaxDynamicSharedMemorySize, SMEM_TOT);
        cudaFuncSetAttribute(k_w,   cudaFuncAttributeMaxDynamicSharedMemorySize, SMEM_TOT);
        cudaFuncSetAttribute(k_x,   cudaFuncAttributeMaxDynamicSharedMemorySize, SMEM_TOT);
        cudaFuncSetAttribute(k_Ax,  cudaFuncAttributeMaxDynamicSharedMemorySize, SMEM_TOT);
        attr_done = true;
    }

    // operand splits
    k_splitA  <<<(2*Mq*Nq/4 + 255)/256, 256>>>(A);
    k_splitAT <<<dim3(Nq/32, TMq/32), dim3(32,8)>>>(A);
    k_split_rn<<<(Bq*2*Nq/4 + 255)/256, 256>>>(r_n);

    // Arn = A @ r_n
    k_C12<<<dim3(TMq/BN, 512/BM, CSPLIT), 256, SMEM_TOT>>>();
    k_Arn_combine<<<(Bq*Mq + 255)/256, 256>>>();

    // G = P P^T
    k_G<<<dim3(TMq/BN, TMq/BM, GSPLIT), 256, SMEM_TOT>>>();
    k_S_from_G<<<(Mq*Mq + 255)/256, 256>>>(log_rho);

    // power iteration
    k_pow_init<<<(TMq+255)/256, 256>>>();
    for(int i=0;i<8;i++){
        k_pow_mv<<<TMq, 256>>>();
        k_pow_norm<<<1, 1024>>>();
    }

    // Newton-Schulz (6 iters, symmetrized)
    k_X_init<<<(TMq*TMq + 255)/256, 256>>>(log_rho);
    for(int i=0;i<6;i++){
        k_T1<<<dim3(TMq/BN, TMq/BM), 256, SMEM_TOT>>>();
        k_T2<<<dim3(TMq/BN, TMq/BM), 256, SMEM_TOT>>>();
        k_newton_upd<<<(TMq*TMq + 255)/256, 256>>>();
    }

    // ADMM loop
    k_init_V<<<(Bq*TMq + 255)/256, 256>>>(y, u_in);
    for(int step=0;step<5;step++){
        k_w <<<dim3(TMq/BN, Bq/BM),          256, SMEM_TOT>>>(ns, step);
        k_x <<<dim3(Nq/BN,  Bq/BM),          256, SMEM_TOT>>>(r_n, ns, step);
        k_Ax<<<dim3(TMq/BN, Bq/BM, NSPLIT),  256, SMEM_TOT>>>(ns, step);
        k_zu<<<Bq, 256>>>(y, log_eps, ns, step);
    }

    k_writeout<<<(Bq*2*Nq + Bq*TMq + 255)/256, 256>>>((float*)d_out);
}